// round 4
// baseline (speedup 1.0000x reference)
#include <cuda_runtime.h>
#include <cuda_bf16.h>
#include <cstdint>

// ============================================================
// MoELayer: out[t,o] = sum_e softmax(x@gw+gb)[t,e] * (x[t,:] @ W[e,:,o])
// T=8192 tokens, D_IN=D_OUT=1024, E=8.
// bf16x2 split-precision tensor-core GEMM, gate folded per-expert.
// Dual path: tcgen05 (arch-specific sm_103a pass) / mma.sync HMMA (sm_103 base).
// ============================================================

#define T_TOKENS 8192
#define DIN      1024
#define DOUT     1024
#define N_EXP    8

#define BM 128
#define BN 128

// Shared dynamic smem size for BOTH paths (max of the two layouts).
#define TILE_B   16384               // tcgen05: 128 rows * 128 B
#define STAGE_B  (4 * TILE_B)        // A_hi, A_lo, B_hi, B_lo
#define GEMM_SMEM (1024 + 2 * STAGE_B)   // 132096 B (hmma path uses 81920 of it)

// ---------------- device scratch ----------------------------------------
__device__ float          g_gates[T_TOKENS * N_EXP];
__device__ __nv_bfloat16  g_xh[T_TOKENS * DIN];
__device__ __nv_bfloat16  g_xl[T_TOKENS * DIN];
__device__ __nv_bfloat16  g_wh[N_EXP * DOUT * DIN];   // [e][o][i]  K-major
__device__ __nv_bfloat16  g_wl[N_EXP * DOUT * DIN];

// ---------------- arch-specific feature detection ------------------------
#if defined(__CUDA_ARCH_FEAT_SM103_ALL) || defined(__CUDA_ARCH_FEAT_SM100_ALL) || defined(__CUDA_ARCH_FEAT_SM101_ALL)
#define HAVE_TCGEN05 1
#else
#define HAVE_TCGEN05 0
#endif

// ---------------- common helpers -----------------------------------------
__device__ __forceinline__ uint32_t smem_u32(const void* p) {
    uint32_t a;
    asm("{ .reg .u64 t; cvta.to.shared.u64 t, %1; cvt.u32.u64 %0, t; }"
        : "=r"(a) : "l"(p));
    return a;
}

// ---------------- tcgen05 helpers (only emitted when called) --------------
__device__ __forceinline__ uint32_t elect_one() {
    uint32_t p;
    asm volatile("{\n\t.reg .pred P;\n\telect.sync _|P, 0xFFFFFFFF;\n\t"
                 "selp.b32 %0, 1, 0, P;\n\t}" : "=r"(p));
    return p;
}

#define MBARRIER_INIT(addr, cnt) \
    asm volatile("mbarrier.init.shared.b64 [%0], %1;" :: "r"((uint32_t)(addr)), "r"((uint32_t)(cnt)) : "memory")
#define MBARRIER_INVAL(addr) \
    asm volatile("mbarrier.inval.shared.b64 [%0];" :: "r"((uint32_t)(addr)) : "memory")

#define MBARRIER_WAIT_PARITY(mbar_smem_addr, phase_parity) do { \
    uint32_t _mbar = (uint32_t)(mbar_smem_addr); \
    uint32_t _parity = (uint32_t)(phase_parity); \
    uint32_t _done; \
    asm volatile( \
        "{\n\t.reg .pred p;\n\t" \
        "mbarrier.try_wait.parity.acquire.cta.shared::cta.b64 p, [%1], %2;\n\t" \
        "selp.b32 %0, 1, 0, p;\n\t}" \
        : "=r"(_done) : "r"(_mbar), "r"(_parity) : "memory"); \
    if (!_done) { \
        asm volatile( \
            "{\n\t.reg .pred P1;\n\t" \
            "WAIT_LOOP_%=:\n\t" \
            "mbarrier.try_wait.parity.acquire.cta.shared::cta.b64 P1, [%0], %1, 0x989680;\n\t" \
            "@P1 bra.uni WAIT_DONE_%=;\n\t" \
            "bra.uni WAIT_LOOP_%=;\n\t" \
            "WAIT_DONE_%=:\n\t}" \
            :: "r"(_mbar), "r"(_parity) : "memory"); \
    } \
} while (0)

#define TCGEN05_ALLOC(smem_addr, nCols) \
    asm volatile("tcgen05.alloc.cta_group::1.sync.aligned.shared::cta.b32 [%0], %1;" \
                 :: "r"((uint32_t)(smem_addr)), "r"((uint32_t)(nCols)) : "memory")
#define TCGEN05_DEALLOC(tmem_addr, nCols) \
    asm volatile("tcgen05.dealloc.cta_group::1.sync.aligned.b32 %0, %1;" \
                 :: "r"(tmem_addr), "r"((uint32_t)(nCols)))
#define TCGEN05_RELINQUISH() \
    asm volatile("tcgen05.relinquish_alloc_permit.cta_group::1.sync.aligned;")
#define TCGEN05_COMMIT(mbar) \
    asm volatile("tcgen05.commit.cta_group::1.mbarrier::arrive::one.shared::cluster.b64 [%0];" \
                 :: "r"((uint32_t)(mbar)) : "memory")
#define TCGEN05_WAIT_LD() \
    asm volatile("tcgen05.wait::ld.sync.aligned;" ::: "memory")
#define TCGEN05_FENCE_BEFORE() \
    asm volatile("tcgen05.fence::before_thread_sync;" ::: "memory")
#define TCGEN05_FENCE_AFTER() \
    asm volatile("tcgen05.fence::after_thread_sync;" ::: "memory")
#define FENCE_PROXY_ASYNC_SHARED_CTA() \
    asm volatile("fence.proxy.async.shared::cta;" ::: "memory")

#define TCGEN05_LD_32X32B_X32(r, tmem_addr) \
    asm volatile( \
        "tcgen05.ld.sync.aligned.32x32b.x32.b32 " \
        "{%0, %1, %2, %3, %4, %5, %6, %7, " \
        " %8, %9, %10, %11, %12, %13, %14, %15, " \
        " %16, %17, %18, %19, %20, %21, %22, %23, " \
        " %24, %25, %26, %27, %28, %29, %30, %31}, [%32];" \
        : "=r"((r)[0]),  "=r"((r)[1]),  "=r"((r)[2]),  "=r"((r)[3]), \
          "=r"((r)[4]),  "=r"((r)[5]),  "=r"((r)[6]),  "=r"((r)[7]), \
          "=r"((r)[8]),  "=r"((r)[9]),  "=r"((r)[10]), "=r"((r)[11]), \
          "=r"((r)[12]), "=r"((r)[13]), "=r"((r)[14]), "=r"((r)[15]), \
          "=r"((r)[16]), "=r"((r)[17]), "=r"((r)[18]), "=r"((r)[19]), \
          "=r"((r)[20]), "=r"((r)[21]), "=r"((r)[22]), "=r"((r)[23]), \
          "=r"((r)[24]), "=r"((r)[25]), "=r"((r)[26]), "=r"((r)[27]), \
          "=r"((r)[28]), "=r"((r)[29]), "=r"((r)[30]), "=r"((r)[31]) \
        : "r"(tmem_addr))

#if HAVE_TCGEN05
__device__ __forceinline__ void mma_f16_ss(uint32_t d, uint64_t da, uint64_t db,
                                           uint32_t idesc, uint32_t en) {
    asm volatile(
        "{\n\t.reg .pred p;\n\tsetp.ne.u32 p, %4, 0;\n\t"
        "tcgen05.mma.cta_group::1.kind::f16 [%0], %1, %2, %3, {%5, %5, %5, %5}, p;\n\t}"
        :: "r"(d), "l"(da), "l"(db), "r"(idesc), "r"(en), "r"(0u) : "memory");
}
#endif

__device__ __forceinline__ uint64_t make_desc_sw128(uint32_t base) {
    const uint64_t BASE =
        (uint64_t(2) << 61) | (uint64_t(1) << 46) | (uint64_t(64) << 32) | (uint64_t(1) << 16);
    return BASE | ((uint64_t)(base >> 4) & 0x3FFF);
}

#define SW128(o) ((o) ^ (((o) >> 3) & 0x70))

// ---------------- mma.sync helper (baseline PTX, any sm_80+) --------------
__device__ __forceinline__ void mma_bf16(float* c, const uint32_t* a, const uint32_t* b) {
    asm volatile(
        "mma.sync.aligned.m16n8k16.row.col.f32.bf16.bf16.f32 "
        "{%0,%1,%2,%3}, {%4,%5,%6,%7}, {%8,%9}, {%0,%1,%2,%3};"
        : "+f"(c[0]), "+f"(c[1]), "+f"(c[2]), "+f"(c[3])
        : "r"(a[0]), "r"(a[1]), "r"(a[2]), "r"(a[3]), "r"(b[0]), "r"(b[1]));
}

// ---------------- kernel 1: gate softmax ----------------------------------
__global__ void gate_kernel(const float* __restrict__ x,
                            const float* __restrict__ gw,
                            const float* __restrict__ gb) {
    int gwarp = (blockIdx.x * blockDim.x + threadIdx.x) >> 5;
    int lane = threadIdx.x & 31;
    if (gwarp >= T_TOKENS) return;
    const float* xr = x + (size_t)gwarp * DIN;
    float acc[N_EXP];
#pragma unroll
    for (int e = 0; e < N_EXP; e++) acc[e] = 0.f;
    for (int i = lane; i < DIN; i += 32) {
        float xv = xr[i];
        const float* gwr = gw + (size_t)i * N_EXP;
#pragma unroll
        for (int e = 0; e < N_EXP; e++) acc[e] += xv * gwr[e];
    }
#pragma unroll
    for (int off = 16; off; off >>= 1)
#pragma unroll
        for (int e = 0; e < N_EXP; e++)
            acc[e] += __shfl_xor_sync(0xffffffffu, acc[e], off);
    if (lane == 0) {
        float m = -1e30f;
#pragma unroll
        for (int e = 0; e < N_EXP; e++) { acc[e] += gb[e]; m = fmaxf(m, acc[e]); }
        float s = 0.f;
#pragma unroll
        for (int e = 0; e < N_EXP; e++) { acc[e] = __expf(acc[e] - m); s += acc[e]; }
        float inv = 1.0f / s;
#pragma unroll
        for (int e = 0; e < N_EXP; e++) g_gates[gwarp * N_EXP + e] = acc[e] * inv;
    }
}

// ---------------- kernel 2: split x into bf16 hi/lo -----------------------
__global__ void split_x_kernel(const float* __restrict__ x) {
    int i = blockIdx.x * blockDim.x + threadIdx.x;   // float4 index
    float4 v = ((const float4*)x)[i];
    __nv_bfloat16 h0 = __float2bfloat16(v.x), h1 = __float2bfloat16(v.y);
    __nv_bfloat16 h2 = __float2bfloat16(v.z), h3 = __float2bfloat16(v.w);
    __nv_bfloat16 l0 = __float2bfloat16(v.x - __bfloat162float(h0));
    __nv_bfloat16 l1 = __float2bfloat16(v.y - __bfloat162float(h1));
    __nv_bfloat16 l2 = __float2bfloat16(v.z - __bfloat162float(h2));
    __nv_bfloat16 l3 = __float2bfloat16(v.w - __bfloat162float(h3));
    ((__nv_bfloat162*)g_xh)[2 * i]     = __nv_bfloat162(h0, h1);
    ((__nv_bfloat162*)g_xh)[2 * i + 1] = __nv_bfloat162(h2, h3);
    ((__nv_bfloat162*)g_xl)[2 * i]     = __nv_bfloat162(l0, l1);
    ((__nv_bfloat162*)g_xl)[2 * i + 1] = __nv_bfloat162(l2, l3);
}

// ---------------- kernel 3: transpose + split W ---------------------------
__global__ void wsplit_kernel(const float* __restrict__ w) {
    __shared__ float tile[32][33];
    int e = blockIdx.z;
    int i0 = blockIdx.y * 32;
    int o0 = blockIdx.x * 32;
    int tx = threadIdx.x, ty = threadIdx.y;   // (32, 8)
    const float* wb = w + ((size_t)e << 20);
#pragma unroll
    for (int k = 0; k < 4; k++)
        tile[ty + 8 * k][tx] = wb[(size_t)(i0 + ty + 8 * k) * DOUT + o0 + tx];
    __syncthreads();
#pragma unroll
    for (int k = 0; k < 4; k++) {
        float v = tile[tx][ty + 8 * k];
        __nv_bfloat16 h = __float2bfloat16(v);
        __nv_bfloat16 l = __float2bfloat16(v - __bfloat162float(h));
        size_t idx = ((size_t)e << 20) + (size_t)(o0 + ty + 8 * k) * DIN + i0 + tx;
        g_wh[idx] = h;
        g_wl[idx] = l;
    }
}

// ---------------- kernel 4: main GEMM (dual path) -------------------------
__global__ void __launch_bounds__(256, 1)
moe_gemm_kernel(float* __restrict__ out) {
    extern __shared__ char smem[];
    int tid = threadIdx.x;
    int wid = tid >> 5;
    int lid = tid & 31;
    int nt = blockIdx.x;           // 0..7
    int mt = blockIdx.y;           // 0..63
    int t0 = mt * BM;
    int o0 = nt * BN;

#if HAVE_TCGEN05
    // ================== tcgen05 TMEM path (sm_103a) ======================
    uint32_t sb = smem_u32(smem);
    const uint32_t MB0 = sb + 8, MB1 = sb + 16;
    const uint32_t IDESC = (1u << 4) | (1u << 7) | (1u << 10) |
                           ((BN / 8) << 17) | ((BM / 16) << 24);

    if (wid == 0) TCGEN05_ALLOC(sb, 128);
    if (tid == 0) { MBARRIER_INIT(MB0, 1); MBARRIER_INIT(MB1, 1); }
    __syncthreads();
    uint32_t tb;
    asm volatile("ld.shared.b32 %0, [%1];" : "=r"(tb) : "r"(sb));

    float acc[64];
#pragma unroll
    for (int c = 0; c < 64; c++) acc[c] = 0.f;

    const uint4* Ah4 = (const uint4*)(g_xh + (size_t)t0 * DIN);
    const uint4* Al4 = (const uint4*)(g_xl + (size_t)t0 * DIN);

    int ph0 = 0, ph1 = 0, pend0 = 0, pend1 = 0;
    int half = wid >> 2;                 // 0: cols 0-63, 1: cols 64-127
    int row = (wid & 3) * 32 + lid;      // TMEM lane / token row
    int my_t = t0 + row;

    for (int e = 0; e < N_EXP; e++) {
        const uint4* Bh4 = (const uint4*)(g_wh + ((size_t)e << 20) + (size_t)o0 * DIN);
        const uint4* Bl4 = (const uint4*)(g_wl + ((size_t)e << 20) + (size_t)o0 * DIN);
        bool first = true;

        for (int kc = 0; kc < DIN / 64; kc++) {
            int b = kc & 1;
            if (b == 0) { if (pend0) { MBARRIER_WAIT_PARITY(MB0, ph0); ph0 ^= 1; pend0 = 0; } }
            else        { if (pend1) { MBARRIER_WAIT_PARITY(MB1, ph1); ph1 ^= 1; pend1 = 0; } }

            uint32_t so = 1024 + (uint32_t)b * STAGE_B;
            char* s = smem + so;
#pragma unroll
            for (int j = 0; j < 4; j++) {
                int idx = j * 256 + tid;
                int r2 = idx >> 3;
                int c16 = idx & 7;
                size_t gidx = (size_t)r2 * 128 + kc * 8 + c16;  // uint4 units
                uint4 vah = Ah4[gidx];
                uint4 val = Al4[gidx];
                uint4 vbh = Bh4[gidx];
                uint4 vbl = Bl4[gidx];
                uint32_t sw = SW128((uint32_t)(r2 * 128 + c16 * 16));
                *(uint4*)(s + sw)              = vah;
                *(uint4*)(s + TILE_B + sw)     = val;
                *(uint4*)(s + 2 * TILE_B + sw) = vbh;
                *(uint4*)(s + 3 * TILE_B + sw) = vbl;
            }
            FENCE_PROXY_ASYNC_SHARED_CTA();
            __syncthreads();

            if (wid == 0) {
                TCGEN05_FENCE_AFTER();
                if (elect_one()) {
                    uint64_t dAh = make_desc_sw128(sb + so);
                    uint64_t dAl = make_desc_sw128(sb + so + TILE_B);
                    uint64_t dBh = make_desc_sw128(sb + so + 2 * TILE_B);
                    uint64_t dBl = make_desc_sw128(sb + so + 3 * TILE_B);
#pragma unroll
                    for (int ks = 0; ks < 4; ks++) {
                        uint64_t off = (uint64_t)(ks * 2);   // 16 bf16 = 32 B
                        mma_f16_ss(tb, dAh + off, dBh + off, IDESC,
                                   (first && ks == 0) ? 0u : 1u);
                        mma_f16_ss(tb, dAh + off, dBl + off, IDESC, 1u);
                        mma_f16_ss(tb, dAl + off, dBh + off, IDESC, 1u);
                    }
                    TCGEN05_COMMIT(b == 0 ? MB0 : MB1);
                }
            }
            first = false;
            if (b == 0) pend0 = 1; else pend1 = 1;
        }

        if (pend0) { MBARRIER_WAIT_PARITY(MB0, ph0); ph0 ^= 1; pend0 = 0; }
        if (pend1) { MBARRIER_WAIT_PARITY(MB1, ph1); ph1 ^= 1; pend1 = 0; }
        TCGEN05_FENCE_AFTER();

        float gv = g_gates[my_t * N_EXP + e];
#pragma unroll
        for (int q = 0; q < 2; q++) {
            uint32_t tmp[32];
            TCGEN05_LD_32X32B_X32(tmp, tb + half * 64 + q * 32);
            TCGEN05_WAIT_LD();
#pragma unroll
            for (int c = 0; c < 32; c++)
                acc[q * 32 + c] = fmaf(gv, __uint_as_float(tmp[c]), acc[q * 32 + c]);
        }
        TCGEN05_FENCE_BEFORE();
        __syncthreads();
    }

    float* orow = out + (size_t)my_t * DOUT + o0 + half * 64;
#pragma unroll
    for (int q = 0; q < 16; q++) {
        float4 v = make_float4(acc[4 * q], acc[4 * q + 1], acc[4 * q + 2], acc[4 * q + 3]);
        ((float4*)orow)[q] = v;
    }

    __syncthreads();
    if (tid == 0) { MBARRIER_INVAL(MB0); MBARRIER_INVAL(MB1); }
    __syncthreads();
    if (wid == 0) { TCGEN05_RELINQUISH(); TCGEN05_DEALLOC(tb, 128); }

#else
    // ================== mma.sync HMMA path (plain sm_103) ================
    // smem per stage: Ah @0, Al @10240, Bh @20480, Bl @30720 (rows: 80 B pitch,
    // 32 bf16 of K per row). Two stages, 40960 B each.
    const int wr = wid >> 1;             // 0..3  -> 32 token rows
    const int wc = wid & 1;              // 0..1  -> 64 out cols
    const int tg = lid >> 2;             // groupID 0..7
    const int tig = lid & 3;             // thread-in-group

    float Cc[64];                        // per-expert accum (16 mma tiles x 4)
    float F[64];                         // gated final accum
#pragma unroll
    for (int i = 0; i < 64; i++) { Cc[i] = 0.f; F[i] = 0.f; }

    auto load_chunk = [&](int s, int c) {
        int e = c >> 5, kc = c & 31;
        const uint4* Ah4 = (const uint4*)(g_xh + (size_t)t0 * DIN);
        const uint4* Al4 = (const uint4*)(g_xl + (size_t)t0 * DIN);
        const uint4* Bh4 = (const uint4*)(g_wh + ((size_t)e << 20) + (size_t)o0 * DIN);
        const uint4* Bl4 = (const uint4*)(g_wl + ((size_t)e << 20) + (size_t)o0 * DIN);
        char* dst = smem + s * 40960;
#pragma unroll
        for (int j = 0; j < 2; j++) {
            int idx = j * 256 + tid;          // 0..511  (128 rows x 4 uint4)
            int r2 = idx >> 2;
            int c16 = idx & 3;
            size_t g = (size_t)r2 * 128 + kc * 4 + c16;
            uint32_t so = (uint32_t)r2 * 80 + c16 * 16;
            uint4 vah = Ah4[g];
            uint4 val = Al4[g];
            uint4 vbh = Bh4[g];
            uint4 vbl = Bl4[g];
            *(uint4*)(dst + so)         = vah;
            *(uint4*)(dst + 10240 + so) = val;
            *(uint4*)(dst + 20480 + so) = vbh;
            *(uint4*)(dst + 30720 + so) = vbl;
        }
    };

    auto compute = [&](int s) {
        const char* base = smem + s * 40960;
#pragma unroll
        for (int ks = 0; ks < 2; ks++) {
            int kb = ks * 16;
            uint32_t ah[2][4], al[2][4];
#pragma unroll
            for (int m2 = 0; m2 < 2; m2++) {
                int r0 = wr * 32 + m2 * 16 + tg;
                const char* A0 = base + (uint32_t)r0 * 80 + (kb + tig * 2) * 2;
                ah[m2][0] = *(const uint32_t*)(A0);
                ah[m2][1] = *(const uint32_t*)(A0 + 8 * 80);
                ah[m2][2] = *(const uint32_t*)(A0 + 16);
                ah[m2][3] = *(const uint32_t*)(A0 + 8 * 80 + 16);
                const char* A1 = A0 + 10240;
                al[m2][0] = *(const uint32_t*)(A1);
                al[m2][1] = *(const uint32_t*)(A1 + 8 * 80);
                al[m2][2] = *(const uint32_t*)(A1 + 16);
                al[m2][3] = *(const uint32_t*)(A1 + 8 * 80 + 16);
            }
            uint32_t bh[8][2], bl[8][2];
#pragma unroll
            for (int n2 = 0; n2 < 8; n2++) {
                int nr = wc * 64 + n2 * 8 + tg;
                const char* B0 = base + 20480 + (uint32_t)nr * 80 + (kb + tig * 2) * 2;
                bh[n2][0] = *(const uint32_t*)(B0);
                bh[n2][1] = *(const uint32_t*)(B0 + 16);
                const char* B1 = B0 + 10240;
                bl[n2][0] = *(const uint32_t*)(B1);
                bl[n2][1] = *(const uint32_t*)(B1 + 16);
            }
#pragma unroll
            for (int m2 = 0; m2 < 2; m2++)
#pragma unroll
                for (int n2 = 0; n2 < 8; n2++) {
                    float* c = &Cc[(m2 * 8 + n2) * 4];
                    mma_bf16(c, ah[m2], bh[n2]);   // hi*hi
                    mma_bf16(c, ah[m2], bl[n2]);   // hi*lo
                    mma_bf16(c, al[m2], bh[n2]);   // lo*hi
                }
        }
    };

    load_chunk(0, 0);
    __syncthreads();
    int c = 0;
    for (int e = 0; e < N_EXP; e++) {
        for (int kc = 0; kc < 32; kc++) {
            if (c < 255) load_chunk((c + 1) & 1, c + 1);
            compute(c & 1);
            __syncthreads();
            c++;
        }
        // gate-weighted accumulate, reset per-expert accum
        int rbase = t0 + wr * 32 + tg;
        float g0  = g_gates[(size_t)(rbase)      * N_EXP + e];
        float g8  = g_gates[(size_t)(rbase + 8)  * N_EXP + e];
        float g16 = g_gates[(size_t)(rbase + 16) * N_EXP + e];
        float g24 = g_gates[(size_t)(rbase + 24) * N_EXP + e];
#pragma unroll
        for (int m2 = 0; m2 < 2; m2++) {
            float ga = m2 ? g16 : g0;
            float gb2 = m2 ? g24 : g8;
#pragma unroll
            for (int n2 = 0; n2 < 8; n2++) {
                int i = (m2 * 8 + n2) * 4;
                F[i + 0] = fmaf(ga,  Cc[i + 0], F[i + 0]);
                F[i + 1] = fmaf(ga,  Cc[i + 1], F[i + 1]);
                F[i + 2] = fmaf(gb2, Cc[i + 2], F[i + 2]);
                F[i + 3] = fmaf(gb2, Cc[i + 3], F[i + 3]);
                Cc[i + 0] = 0.f; Cc[i + 1] = 0.f; Cc[i + 2] = 0.f; Cc[i + 3] = 0.f;
            }
        }
    }

    // store
#pragma unroll
    for (int m2 = 0; m2 < 2; m2++)
#pragma unroll
        for (int n2 = 0; n2 < 8; n2++) {
            int i = (m2 * 8 + n2) * 4;
            size_t r = (size_t)(t0 + wr * 32 + m2 * 16 + tg);
            size_t col = (size_t)(o0 + wc * 64 + n2 * 8 + tig * 2);
            float2 v0 = make_float2(F[i + 0], F[i + 1]);
            float2 v1 = make_float2(F[i + 2], F[i + 3]);
            *(float2*)&out[r * DOUT + col]       = v0;
            *(float2*)&out[(r + 8) * DOUT + col] = v1;
        }
#endif
}

// ---------------- launch --------------------------------------------------
extern "C" void kernel_launch(void* const* d_in, const int* in_sizes, int n_in,
                              void* d_out, int out_size) {
    const float* x  = (const float*)d_in[0];
    const float* gw = (const float*)d_in[1];
    const float* gb = (const float*)d_in[2];
    const float* w  = (const float*)d_in[3];
    float* out = (float*)d_out;

    gate_kernel<<<T_TOKENS / 8, 256>>>(x, gw, gb);
    split_x_kernel<<<(T_TOKENS * DIN / 4) / 256, 256>>>(x);
    wsplit_kernel<<<dim3(DOUT / 32, DIN / 32, N_EXP), dim3(32, 8)>>>(w);

    cudaFuncSetAttribute(moe_gemm_kernel,
                         cudaFuncAttributeMaxDynamicSharedMemorySize, GEMM_SMEM);
    moe_gemm_kernel<<<dim3(DOUT / BN, T_TOKENS / BM), 256, GEMM_SMEM>>>(out);
}

// round 5
// speedup vs baseline: 1.4582x; 1.4582x over previous
#include <cuda_runtime.h>
#include <cuda_bf16.h>
#include <cstdint>

// ============================================================
// MoELayer: out[t,o] = sum_e softmax(x@gw+gb)[t,e] * (x[t,:] @ W[e,:,o])
// T=8192 tokens, D_IN=D_OUT=1024, E=8.
// bf16x2 split-precision tensor-core GEMM, gate folded per-expert.
// Dual path: tcgen05 (arch-specific pass) / mma.sync HMMA (baseline).
// R5: BM=256 (B-tile reuse across 2 M-blocks), cross-expert prefetch.
// ============================================================

#define T_TOKENS 8192
#define DIN      1024
#define DOUT     1024
#define N_EXP    8

#define BM 256              // tokens per CTA (2 x 128 M-blocks)
#define BN 128              // out cols per CTA
#define BK 64               // K chunk

// tcgen05 smem: 6 tensors x 16 KB per stage (A0h A0l A1h A1l Bh Bl)
#define TEN_B    16384
#define STAGE_B  (6 * TEN_B)                 // 98304
#define GEMM_SMEM (1024 + 2 * STAGE_B)       // 197632 (hmma path uses 81920)

// ---------------- device scratch ----------------------------------------
__device__ float          g_gates[T_TOKENS * N_EXP];
__device__ __nv_bfloat16  g_xh[T_TOKENS * DIN];
__device__ __nv_bfloat16  g_xl[T_TOKENS * DIN];
__device__ __nv_bfloat16  g_wh[N_EXP * DOUT * DIN];   // [e][o][i]  K-major
__device__ __nv_bfloat16  g_wl[N_EXP * DOUT * DIN];

// ---------------- arch-specific feature detection ------------------------
#if defined(__CUDA_ARCH_FEAT_SM103_ALL) || defined(__CUDA_ARCH_FEAT_SM100_ALL) || defined(__CUDA_ARCH_FEAT_SM101_ALL)
#define HAVE_TCGEN05 1
#else
#define HAVE_TCGEN05 0
#endif

// ---------------- common helpers -----------------------------------------
__device__ __forceinline__ uint32_t smem_u32(const void* p) {
    uint32_t a;
    asm("{ .reg .u64 t; cvta.to.shared.u64 t, %1; cvt.u32.u64 %0, t; }"
        : "=r"(a) : "l"(p));
    return a;
}

__device__ __forceinline__ uint32_t elect_one() {
    uint32_t p;
    asm volatile("{\n\t.reg .pred P;\n\telect.sync _|P, 0xFFFFFFFF;\n\t"
                 "selp.b32 %0, 1, 0, P;\n\t}" : "=r"(p));
    return p;
}

#define MBARRIER_INIT(addr, cnt) \
    asm volatile("mbarrier.init.shared.b64 [%0], %1;" :: "r"((uint32_t)(addr)), "r"((uint32_t)(cnt)) : "memory")
#define MBARRIER_INVAL(addr) \
    asm volatile("mbarrier.inval.shared.b64 [%0];" :: "r"((uint32_t)(addr)) : "memory")

#define MBARRIER_WAIT_PARITY(mbar_smem_addr, phase_parity) do { \
    uint32_t _mbar = (uint32_t)(mbar_smem_addr); \
    uint32_t _parity = (uint32_t)(phase_parity); \
    uint32_t _done; \
    asm volatile( \
        "{\n\t.reg .pred p;\n\t" \
        "mbarrier.try_wait.parity.acquire.cta.shared::cta.b64 p, [%1], %2;\n\t" \
        "selp.b32 %0, 1, 0, p;\n\t}" \
        : "=r"(_done) : "r"(_mbar), "r"(_parity) : "memory"); \
    if (!_done) { \
        asm volatile( \
            "{\n\t.reg .pred P1;\n\t" \
            "WAIT_LOOP_%=:\n\t" \
            "mbarrier.try_wait.parity.acquire.cta.shared::cta.b64 P1, [%0], %1, 0x989680;\n\t" \
            "@P1 bra.uni WAIT_DONE_%=;\n\t" \
            "bra.uni WAIT_LOOP_%=;\n\t" \
            "WAIT_DONE_%=:\n\t}" \
            :: "r"(_mbar), "r"(_parity) : "memory"); \
    } \
} while (0)

#define TCGEN05_ALLOC(smem_addr, nCols) \
    asm volatile("tcgen05.alloc.cta_group::1.sync.aligned.shared::cta.b32 [%0], %1;" \
                 :: "r"((uint32_t)(smem_addr)), "r"((uint32_t)(nCols)) : "memory")
#define TCGEN05_DEALLOC(tmem_addr, nCols) \
    asm volatile("tcgen05.dealloc.cta_group::1.sync.aligned.b32 %0, %1;" \
                 :: "r"(tmem_addr), "r"((uint32_t)(nCols)))
#define TCGEN05_RELINQUISH() \
    asm volatile("tcgen05.relinquish_alloc_permit.cta_group::1.sync.aligned;")
#define TCGEN05_COMMIT(mbar) \
    asm volatile("tcgen05.commit.cta_group::1.mbarrier::arrive::one.shared::cluster.b64 [%0];" \
                 :: "r"((uint32_t)(mbar)) : "memory")
#define TCGEN05_WAIT_LD() \
    asm volatile("tcgen05.wait::ld.sync.aligned;" ::: "memory")
#define TCGEN05_FENCE_BEFORE() \
    asm volatile("tcgen05.fence::before_thread_sync;" ::: "memory")
#define TCGEN05_FENCE_AFTER() \
    asm volatile("tcgen05.fence::after_thread_sync;" ::: "memory")
#define FENCE_PROXY_ASYNC_SHARED_CTA() \
    asm volatile("fence.proxy.async.shared::cta;" ::: "memory")

#define TCGEN05_LD_32X32B_X32(r, tmem_addr) \
    asm volatile( \
        "tcgen05.ld.sync.aligned.32x32b.x32.b32 " \
        "{%0, %1, %2, %3, %4, %5, %6, %7, " \
        " %8, %9, %10, %11, %12, %13, %14, %15, " \
        " %16, %17, %18, %19, %20, %21, %22, %23, " \
        " %24, %25, %26, %27, %28, %29, %30, %31}, [%32];" \
        : "=r"((r)[0]),  "=r"((r)[1]),  "=r"((r)[2]),  "=r"((r)[3]), \
          "=r"((r)[4]),  "=r"((r)[5]),  "=r"((r)[6]),  "=r"((r)[7]), \
          "=r"((r)[8]),  "=r"((r)[9]),  "=r"((r)[10]), "=r"((r)[11]), \
          "=r"((r)[12]), "=r"((r)[13]), "=r"((r)[14]), "=r"((r)[15]), \
          "=r"((r)[16]), "=r"((r)[17]), "=r"((r)[18]), "=r"((r)[19]), \
          "=r"((r)[20]), "=r"((r)[21]), "=r"((r)[22]), "=r"((r)[23]), \
          "=r"((r)[24]), "=r"((r)[25]), "=r"((r)[26]), "=r"((r)[27]), \
          "=r"((r)[28]), "=r"((r)[29]), "=r"((r)[30]), "=r"((r)[31]) \
        : "r"(tmem_addr))

#if HAVE_TCGEN05
__device__ __forceinline__ void mma_f16_ss(uint32_t d, uint64_t da, uint64_t db,
                                           uint32_t idesc, uint32_t en) {
    asm volatile(
        "{\n\t.reg .pred p;\n\tsetp.ne.u32 p, %4, 0;\n\t"
        "tcgen05.mma.cta_group::1.kind::f16 [%0], %1, %2, %3, {%5, %5, %5, %5}, p;\n\t}"
        :: "r"(d), "l"(da), "l"(db), "r"(idesc), "r"(en), "r"(0u) : "memory");
}
#endif

__device__ __forceinline__ uint64_t make_desc_sw128(uint32_t base) {
    const uint64_t BASE =
        (uint64_t(2) << 61) | (uint64_t(1) << 46) | (uint64_t(64) << 32) | (uint64_t(1) << 16);
    return BASE | ((uint64_t)(base >> 4) & 0x3FFF);
}

#define SW128(o) ((o) ^ (((o) >> 3) & 0x70))

// ---------------- mma.sync helper (baseline PTX) --------------------------
__device__ __forceinline__ void mma_bf16(float* c, const uint32_t* a, const uint32_t* b) {
    asm volatile(
        "mma.sync.aligned.m16n8k16.row.col.f32.bf16.bf16.f32 "
        "{%0,%1,%2,%3}, {%4,%5,%6,%7}, {%8,%9}, {%0,%1,%2,%3};"
        : "+f"(c[0]), "+f"(c[1]), "+f"(c[2]), "+f"(c[3])
        : "r"(a[0]), "r"(a[1]), "r"(a[2]), "r"(a[3]), "r"(b[0]), "r"(b[1]));
}

// ---------------- kernel 1: gate softmax ----------------------------------
__global__ void gate_kernel(const float* __restrict__ x,
                            const float* __restrict__ gw,
                            const float* __restrict__ gb) {
    int gwarp = (blockIdx.x * blockDim.x + threadIdx.x) >> 5;
    int lane = threadIdx.x & 31;
    if (gwarp >= T_TOKENS) return;
    const float* xr = x + (size_t)gwarp * DIN;
    float acc[N_EXP];
#pragma unroll
    for (int e = 0; e < N_EXP; e++) acc[e] = 0.f;
    for (int i = lane; i < DIN; i += 32) {
        float xv = xr[i];
        const float* gwr = gw + (size_t)i * N_EXP;
#pragma unroll
        for (int e = 0; e < N_EXP; e++) acc[e] += xv * gwr[e];
    }
#pragma unroll
    for (int off = 16; off; off >>= 1)
#pragma unroll
        for (int e = 0; e < N_EXP; e++)
            acc[e] += __shfl_xor_sync(0xffffffffu, acc[e], off);
    if (lane == 0) {
        float m = -1e30f;
#pragma unroll
        for (int e = 0; e < N_EXP; e++) { acc[e] += gb[e]; m = fmaxf(m, acc[e]); }
        float s = 0.f;
#pragma unroll
        for (int e = 0; e < N_EXP; e++) { acc[e] = __expf(acc[e] - m); s += acc[e]; }
        float inv = 1.0f / s;
#pragma unroll
        for (int e = 0; e < N_EXP; e++) g_gates[gwarp * N_EXP + e] = acc[e] * inv;
    }
}

// ---------------- kernel 2: split x into bf16 hi/lo -----------------------
__global__ void split_x_kernel(const float* __restrict__ x) {
    int i = blockIdx.x * blockDim.x + threadIdx.x;   // float4 index
    float4 v = ((const float4*)x)[i];
    __nv_bfloat16 h0 = __float2bfloat16(v.x), h1 = __float2bfloat16(v.y);
    __nv_bfloat16 h2 = __float2bfloat16(v.z), h3 = __float2bfloat16(v.w);
    __nv_bfloat16 l0 = __float2bfloat16(v.x - __bfloat162float(h0));
    __nv_bfloat16 l1 = __float2bfloat16(v.y - __bfloat162float(h1));
    __nv_bfloat16 l2 = __float2bfloat16(v.z - __bfloat162float(h2));
    __nv_bfloat16 l3 = __float2bfloat16(v.w - __bfloat162float(h3));
    ((__nv_bfloat162*)g_xh)[2 * i]     = __nv_bfloat162(h0, h1);
    ((__nv_bfloat162*)g_xh)[2 * i + 1] = __nv_bfloat162(h2, h3);
    ((__nv_bfloat162*)g_xl)[2 * i]     = __nv_bfloat162(l0, l1);
    ((__nv_bfloat162*)g_xl)[2 * i + 1] = __nv_bfloat162(l2, l3);
}

// ---------------- kernel 3: transpose + split W ---------------------------
__global__ void wsplit_kernel(const float* __restrict__ w) {
    __shared__ float tile[32][33];
    int e = blockIdx.z;
    int i0 = blockIdx.y * 32;
    int o0 = blockIdx.x * 32;
    int tx = threadIdx.x, ty = threadIdx.y;   // (32, 8)
    const float* wb = w + ((size_t)e << 20);
#pragma unroll
    for (int k = 0; k < 4; k++)
        tile[ty + 8 * k][tx] = wb[(size_t)(i0 + ty + 8 * k) * DOUT + o0 + tx];
    __syncthreads();
#pragma unroll
    for (int k = 0; k < 4; k++) {
        float v = tile[tx][ty + 8 * k];
        __nv_bfloat16 h = __float2bfloat16(v);
        __nv_bfloat16 l = __float2bfloat16(v - __bfloat162float(h));
        size_t idx = ((size_t)e << 20) + (size_t)(o0 + ty + 8 * k) * DIN + i0 + tx;
        g_wh[idx] = h;
        g_wl[idx] = l;
    }
}

// ---------------- kernel 4: main GEMM (dual path) -------------------------
__global__ void __launch_bounds__(256, 1)
moe_gemm_kernel(float* __restrict__ out) {
    extern __shared__ char smem[];
    int tid = threadIdx.x;
    int wid = tid >> 5;
    int lid = tid & 31;
    int nt = blockIdx.x;           // 0..7
    int mt = blockIdx.y;           // 0..31
    int t0 = mt * BM;
    int o0 = nt * BN;

#if HAVE_TCGEN05
    // ================== tcgen05 TMEM path (sm_103a) ======================
    // BM=256: two 128-row M-blocks share the B tile. D: block0 -> TMEM cols
    // [0,128), block1 -> [128,256). Flat chunk loop with cross-expert prefetch.
    uint32_t sb = smem_u32(smem);
    const uint32_t MB[2] = {sb + 8, sb + 16};
    const uint32_t IDESC = (1u << 4) | (1u << 7) | (1u << 10) |
                           ((BN / 8) << 17) | ((128 / 16) << 24);

    if (wid == 0) TCGEN05_ALLOC(sb, 256);
    if (tid == 0) { MBARRIER_INIT(MB[0], 1); MBARRIER_INIT(MB[1], 1); }
    __syncthreads();
    uint32_t tb;
    asm volatile("ld.shared.b32 %0, [%1];" : "=r"(tb) : "r"(sb));

    // this thread's output row / column half
    int mblk = wid >> 2;                       // 0 or 1 (M-block)
    int row_in_blk = (wid & 3) * 32 + lid;     // 0..127
    int my_t = t0 + mblk * 128 + row_in_blk;

    float gv[N_EXP];
#pragma unroll
    for (int e = 0; e < N_EXP; e++) gv[e] = g_gates[(size_t)my_t * N_EXP + e];

    float F[BN];
#pragma unroll
    for (int c = 0; c < BN; c++) F[c] = 0.f;

    const uint4* A0h = (const uint4*)(g_xh + (size_t)t0 * DIN);
    const uint4* A0l = (const uint4*)(g_xl + (size_t)t0 * DIN);
    const uint4* A1h = (const uint4*)(g_xh + (size_t)(t0 + 128) * DIN);
    const uint4* A1l = (const uint4*)(g_xl + (size_t)(t0 + 128) * DIN);

    int ph[2] = {0, 0}, pend[2] = {0, 0};
    const int CHUNKS = N_EXP * (DIN / BK);     // 128

    for (int c = 0; c < CHUNKS; c++) {
        int b = c & 1;
        int e = c >> 4, kc = c & 15;
        if (pend[b]) { MBARRIER_WAIT_PARITY(MB[b], ph[b]); ph[b] ^= 1; pend[b] = 0; }

        // ---- load chunk c into stage b (6 x 16 KB) ----
        {
            const uint4* Bh = (const uint4*)(g_wh + ((size_t)e << 20) + (size_t)o0 * DIN);
            const uint4* Bl = (const uint4*)(g_wl + ((size_t)e << 20) + (size_t)o0 * DIN);
            char* s = smem + 1024 + (uint32_t)b * STAGE_B;
#pragma unroll
            for (int j = 0; j < 4; j++) {
                int idx = j * 256 + tid;            // 0..1023
                int r2 = idx >> 3;                  // row 0..127
                int c16 = idx & 7;                  // uint4 within row
                size_t g = (size_t)r2 * 128 + kc * 8 + c16;
                uint4 v0 = A0h[g];
                uint4 v1 = A0l[g];
                uint4 v2 = A1h[g];
                uint4 v3 = A1l[g];
                uint4 v4 = Bh[g];
                uint4 v5 = Bl[g];
                uint32_t sw = SW128((uint32_t)(r2 * 128 + c16 * 16));
                *(uint4*)(s + sw)             = v0;
                *(uint4*)(s + TEN_B + sw)     = v1;
                *(uint4*)(s + 2 * TEN_B + sw) = v2;
                *(uint4*)(s + 3 * TEN_B + sw) = v3;
                *(uint4*)(s + 4 * TEN_B + sw) = v4;
                *(uint4*)(s + 5 * TEN_B + sw) = v5;
            }
        }
        FENCE_PROXY_ASYNC_SHARED_CTA();
        __syncthreads();

        // ---- at expert boundary: drain prev expert, epilogue (loads above
        //      already overlap the tail MMAs of the previous expert) ----
        if (kc == 0 && c > 0) {
            int ob = b ^ 1;
            if (pend[ob]) { MBARRIER_WAIT_PARITY(MB[ob], ph[ob]); ph[ob] ^= 1; pend[ob] = 0; }
            TCGEN05_FENCE_AFTER();
            float g0 = gv[e - 1];
#pragma unroll
            for (int q = 0; q < 4; q++) {
                uint32_t tmp[32];
                TCGEN05_LD_32X32B_X32(tmp, tb + mblk * 128 + q * 32);
                TCGEN05_WAIT_LD();
#pragma unroll
                for (int cc = 0; cc < 32; cc++)
                    F[q * 32 + cc] = fmaf(g0, __uint_as_float(tmp[cc]), F[q * 32 + cc]);
            }
            TCGEN05_FENCE_BEFORE();
            __syncthreads();
        }

        // ---- issue MMAs for chunk c ----
        if (wid == 0) {
            TCGEN05_FENCE_AFTER();
            if (elect_one()) {
                uint32_t so = sb + 1024 + (uint32_t)b * STAGE_B;
                uint64_t dA0h = make_desc_sw128(so);
                uint64_t dA0l = make_desc_sw128(so + TEN_B);
                uint64_t dA1h = make_desc_sw128(so + 2 * TEN_B);
                uint64_t dA1l = make_desc_sw128(so + 3 * TEN_B);
                uint64_t dBh  = make_desc_sw128(so + 4 * TEN_B);
                uint64_t dBl  = make_desc_sw128(so + 5 * TEN_B);
#pragma unroll
                for (int ks = 0; ks < 4; ks++) {
                    uint64_t off = (uint64_t)(ks * 2);     // 16 bf16 = 32 B
                    uint32_t en0 = (kc == 0 && ks == 0) ? 0u : 1u;
                    // M-block 0 -> D cols [0,128)
                    mma_f16_ss(tb,       dA0h + off, dBh + off, IDESC, en0);
                    mma_f16_ss(tb,       dA0h + off, dBl + off, IDESC, 1u);
                    mma_f16_ss(tb,       dA0l + off, dBh + off, IDESC, 1u);
                    // M-block 1 -> D cols [128,256)
                    mma_f16_ss(tb + 128, dA1h + off, dBh + off, IDESC, en0);
                    mma_f16_ss(tb + 128, dA1h + off, dBl + off, IDESC, 1u);
                    mma_f16_ss(tb + 128, dA1l + off, dBh + off, IDESC, 1u);
                }
                TCGEN05_COMMIT(MB[b]);
            }
        }
        pend[b] = 1;
    }

    // ---- tail: drain + epilogue for expert 7 ----
    if (pend[0]) { MBARRIER_WAIT_PARITY(MB[0], ph[0]); ph[0] ^= 1; pend[0] = 0; }
    if (pend[1]) { MBARRIER_WAIT_PARITY(MB[1], ph[1]); ph[1] ^= 1; pend[1] = 0; }
    TCGEN05_FENCE_AFTER();
    {
        float g0 = gv[N_EXP - 1];
#pragma unroll
        for (int q = 0; q < 4; q++) {
            uint32_t tmp[32];
            TCGEN05_LD_32X32B_X32(tmp, tb + mblk * 128 + q * 32);
            TCGEN05_WAIT_LD();
#pragma unroll
            for (int cc = 0; cc < 32; cc++)
                F[q * 32 + cc] = fmaf(g0, __uint_as_float(tmp[cc]), F[q * 32 + cc]);
        }
    }
    TCGEN05_FENCE_BEFORE();

    // store out tile (fp32): row my_t, cols [o0, o0+128)
    float* orow = out + (size_t)my_t * DOUT + o0;
#pragma unroll
    for (int q = 0; q < BN / 4; q++) {
        float4 v = make_float4(F[4 * q], F[4 * q + 1], F[4 * q + 2], F[4 * q + 3]);
        ((float4*)orow)[q] = v;
    }

    __syncthreads();
    if (tid == 0) { MBARRIER_INVAL(MB[0]); MBARRIER_INVAL(MB[1]); }
    __syncthreads();
    if (wid == 0) { TCGEN05_RELINQUISH(); TCGEN05_DEALLOC(tb, 256); }

#else
    // ================== mma.sync HMMA path (baseline) ====================
    // BM=256 handled as two sequential 128-row halves (compute-bound path).
    const int wr = wid >> 1;             // 0..3  -> 32 token rows
    const int wc = wid & 1;              // 0..1  -> 64 out cols
    const int tg = lid >> 2;             // groupID 0..7
    const int tig = lid & 3;             // thread-in-group

    for (int half = 0; half < 2; half++) {
        int t0h = t0 + half * 128;

        float Cc[64];
        float F[64];
#pragma unroll
        for (int i = 0; i < 64; i++) { Cc[i] = 0.f; F[i] = 0.f; }

        auto load_chunk = [&](int s, int c) {
            int e = c >> 5, kc = c & 31;
            const uint4* Ah4 = (const uint4*)(g_xh + (size_t)t0h * DIN);
            const uint4* Al4 = (const uint4*)(g_xl + (size_t)t0h * DIN);
            const uint4* Bh4 = (const uint4*)(g_wh + ((size_t)e << 20) + (size_t)o0 * DIN);
            const uint4* Bl4 = (const uint4*)(g_wl + ((size_t)e << 20) + (size_t)o0 * DIN);
            char* dst = smem + s * 40960;
#pragma unroll
            for (int j = 0; j < 2; j++) {
                int idx = j * 256 + tid;          // 0..511
                int r2 = idx >> 2;
                int c16 = idx & 3;
                size_t g = (size_t)r2 * 128 + kc * 4 + c16;
                uint32_t so = (uint32_t)r2 * 80 + c16 * 16;
                uint4 vah = Ah4[g];
                uint4 val = Al4[g];
                uint4 vbh = Bh4[g];
                uint4 vbl = Bl4[g];
                *(uint4*)(dst + so)         = vah;
                *(uint4*)(dst + 10240 + so) = val;
                *(uint4*)(dst + 20480 + so) = vbh;
                *(uint4*)(dst + 30720 + so) = vbl;
            }
        };

        auto compute = [&](int s) {
            const char* base = smem + s * 40960;
#pragma unroll
            for (int ks = 0; ks < 2; ks++) {
                int kb = ks * 16;
                uint32_t ah[2][4], al[2][4];
#pragma unroll
                for (int m2 = 0; m2 < 2; m2++) {
                    int r0 = wr * 32 + m2 * 16 + tg;
                    const char* A0 = base + (uint32_t)r0 * 80 + (kb + tig * 2) * 2;
                    ah[m2][0] = *(const uint32_t*)(A0);
                    ah[m2][1] = *(const uint32_t*)(A0 + 8 * 80);
                    ah[m2][2] = *(const uint32_t*)(A0 + 16);
                    ah[m2][3] = *(const uint32_t*)(A0 + 8 * 80 + 16);
                    const char* A1 = A0 + 10240;
                    al[m2][0] = *(const uint32_t*)(A1);
                    al[m2][1] = *(const uint32_t*)(A1 + 8 * 80);
                    al[m2][2] = *(const uint32_t*)(A1 + 16);
                    al[m2][3] = *(const uint32_t*)(A1 + 8 * 80 + 16);
                }
                uint32_t bh[8][2], bl[8][2];
#pragma unroll
                for (int n2 = 0; n2 < 8; n2++) {
                    int nr = wc * 64 + n2 * 8 + tg;
                    const char* B0 = base + 20480 + (uint32_t)nr * 80 + (kb + tig * 2) * 2;
                    bh[n2][0] = *(const uint32_t*)(B0);
                    bh[n2][1] = *(const uint32_t*)(B0 + 16);
                    const char* B1 = B0 + 10240;
                    bl[n2][0] = *(const uint32_t*)(B1);
                    bl[n2][1] = *(const uint32_t*)(B1 + 16);
                }
#pragma unroll
                for (int m2 = 0; m2 < 2; m2++)
#pragma unroll
                    for (int n2 = 0; n2 < 8; n2++) {
                        float* c = &Cc[(m2 * 8 + n2) * 4];
                        mma_bf16(c, ah[m2], bh[n2]);   // hi*hi
                        mma_bf16(c, ah[m2], bl[n2]);   // hi*lo
                        mma_bf16(c, al[m2], bh[n2]);   // lo*hi
                    }
            }
        };

        load_chunk(0, 0);
        __syncthreads();
        int c = 0;
        for (int e = 0; e < N_EXP; e++) {
            for (int kc = 0; kc < 32; kc++) {
                if (c < 255) load_chunk((c + 1) & 1, c + 1);
                compute(c & 1);
                __syncthreads();
                c++;
            }
            int rbase = t0h + wr * 32 + tg;
            float g0  = g_gates[(size_t)(rbase)      * N_EXP + e];
            float g8  = g_gates[(size_t)(rbase + 8)  * N_EXP + e];
            float g16 = g_gates[(size_t)(rbase + 16) * N_EXP + e];
            float g24 = g_gates[(size_t)(rbase + 24) * N_EXP + e];
#pragma unroll
            for (int m2 = 0; m2 < 2; m2++) {
                float ga = m2 ? g16 : g0;
                float gb2 = m2 ? g24 : g8;
#pragma unroll
                for (int n2 = 0; n2 < 8; n2++) {
                    int i = (m2 * 8 + n2) * 4;
                    F[i + 0] = fmaf(ga,  Cc[i + 0], F[i + 0]);
                    F[i + 1] = fmaf(ga,  Cc[i + 1], F[i + 1]);
                    F[i + 2] = fmaf(gb2, Cc[i + 2], F[i + 2]);
                    F[i + 3] = fmaf(gb2, Cc[i + 3], F[i + 3]);
                    Cc[i + 0] = 0.f; Cc[i + 1] = 0.f; Cc[i + 2] = 0.f; Cc[i + 3] = 0.f;
                }
            }
        }

#pragma unroll
        for (int m2 = 0; m2 < 2; m2++)
#pragma unroll
            for (int n2 = 0; n2 < 8; n2++) {
                int i = (m2 * 8 + n2) * 4;
                size_t r = (size_t)(t0h + wr * 32 + m2 * 16 + tg);
                size_t col = (size_t)(o0 + wc * 64 + n2 * 8 + tig * 2);
                float2 v0 = make_float2(F[i + 0], F[i + 1]);
                float2 v1 = make_float2(F[i + 2], F[i + 3]);
                *(float2*)&out[r * DOUT + col]       = v0;
                *(float2*)&out[(r + 8) * DOUT + col] = v1;
            }
        __syncthreads();
    }
#endif
}

// ---------------- launch --------------------------------------------------
extern "C" void kernel_launch(void* const* d_in, const int* in_sizes, int n_in,
                              void* d_out, int out_size) {
    const float* x  = (const float*)d_in[0];
    const float* gw = (const float*)d_in[1];
    const float* gb = (const float*)d_in[2];
    const float* w  = (const float*)d_in[3];
    float* out = (float*)d_out;

    gate_kernel<<<T_TOKENS / 8, 256>>>(x, gw, gb);
    split_x_kernel<<<(T_TOKENS * DIN / 4) / 256, 256>>>(x);
    wsplit_kernel<<<dim3(DOUT / 32, DIN / 32, N_EXP), dim3(32, 8)>>>(w);

    cudaFuncSetAttribute(moe_gemm_kernel,
                         cudaFuncAttributeMaxDynamicSharedMemorySize, GEMM_SMEM);
    moe_gemm_kernel<<<dim3(DOUT / BN, T_TOKENS / BM), 256, GEMM_SMEM>>>(out);
}

// round 6
// speedup vs baseline: 2.2177x; 1.5208x over previous
#include <cuda_runtime.h>
#include <cuda_bf16.h>
#include <cstdint>

// ============================================================
// MoELayer: out[t,o] = sum_e softmax(x@gw+gb)[t,e] * (x[t,:] @ W[e,:,o])
// T=8192, D_IN=D_OUT=1024, E=8.
// R6: gate folded into A (prescaled per-expert A'_e = g*x, bf16 hi/lo split)
//     -> single TMEM accumulation across all experts, no per-expert epilogue.
//     cp.async 3-stage pipeline, BK=32 (SW64), BM=256 x BN=256, 128 CTAs.
// ============================================================

#define T_TOKENS 8192
#define DIN      1024
#define DOUT     1024
#define N_EXP    8

#define BM 256              // tokens per CTA (2 x 128 M-blocks)
#define BN 256              // out cols per CTA (2 x 128 N-blocks)
#define BK 32               // K chunk (64 B rows, SW64)

#define TILE_B   8192                     // 128 rows * 64 B
#define STAGE_B  (8 * TILE_B)             // A0h A0l A1h A1l B0h B0l B1h B1l = 64 KB
#define NSTAGE   3
#define GEMM_SMEM (1024 + NSTAGE * STAGE_B)   // 197632

// ---------------- device scratch ----------------------------------------
__device__ float          g_gates[T_TOKENS * N_EXP];
// per-expert gate-prescaled activations, bf16 hi/lo split: [e][t][i]
__device__ __nv_bfloat16  g_axh[(size_t)N_EXP * T_TOKENS * DIN];
__device__ __nv_bfloat16  g_axl[(size_t)N_EXP * T_TOKENS * DIN];
__device__ __nv_bfloat16  g_wh[N_EXP * DOUT * DIN];   // [e][o][i]  K-major
__device__ __nv_bfloat16  g_wl[N_EXP * DOUT * DIN];

// ---------------- arch-specific feature detection ------------------------
#if defined(__CUDA_ARCH_FEAT_SM103_ALL) || defined(__CUDA_ARCH_FEAT_SM100_ALL) || defined(__CUDA_ARCH_FEAT_SM101_ALL)
#define HAVE_TCGEN05 1
#else
#define HAVE_TCGEN05 0
#endif

// ---------------- common helpers -----------------------------------------
__device__ __forceinline__ uint32_t smem_u32(const void* p) {
    uint32_t a;
    asm("{ .reg .u64 t; cvta.to.shared.u64 t, %1; cvt.u32.u64 %0, t; }"
        : "=r"(a) : "l"(p));
    return a;
}

__device__ __forceinline__ uint32_t elect_one() {
    uint32_t p;
    asm volatile("{\n\t.reg .pred P;\n\telect.sync _|P, 0xFFFFFFFF;\n\t"
                 "selp.b32 %0, 1, 0, P;\n\t}" : "=r"(p));
    return p;
}

#define MBARRIER_INIT(addr, cnt) \
    asm volatile("mbarrier.init.shared.b64 [%0], %1;" :: "r"((uint32_t)(addr)), "r"((uint32_t)(cnt)) : "memory")
#define MBARRIER_INVAL(addr) \
    asm volatile("mbarrier.inval.shared.b64 [%0];" :: "r"((uint32_t)(addr)) : "memory")

#define MBARRIER_WAIT_PARITY(mbar_smem_addr, phase_parity) do { \
    uint32_t _mbar = (uint32_t)(mbar_smem_addr); \
    uint32_t _parity = (uint32_t)(phase_parity); \
    uint32_t _done; \
    asm volatile( \
        "{\n\t.reg .pred p;\n\t" \
        "mbarrier.try_wait.parity.acquire.cta.shared::cta.b64 p, [%1], %2;\n\t" \
        "selp.b32 %0, 1, 0, p;\n\t}" \
        : "=r"(_done) : "r"(_mbar), "r"(_parity) : "memory"); \
    if (!_done) { \
        asm volatile( \
            "{\n\t.reg .pred P1;\n\t" \
            "WAIT_LOOP_%=:\n\t" \
            "mbarrier.try_wait.parity.acquire.cta.shared::cta.b64 P1, [%0], %1, 0x989680;\n\t" \
            "@P1 bra.uni WAIT_DONE_%=;\n\t" \
            "bra.uni WAIT_LOOP_%=;\n\t" \
            "WAIT_DONE_%=:\n\t}" \
            :: "r"(_mbar), "r"(_parity) : "memory"); \
    } \
} while (0)

#define TCGEN05_ALLOC(smem_addr, nCols) \
    asm volatile("tcgen05.alloc.cta_group::1.sync.aligned.shared::cta.b32 [%0], %1;" \
                 :: "r"((uint32_t)(smem_addr)), "r"((uint32_t)(nCols)) : "memory")
#define TCGEN05_DEALLOC(tmem_addr, nCols) \
    asm volatile("tcgen05.dealloc.cta_group::1.sync.aligned.b32 %0, %1;" \
                 :: "r"(tmem_addr), "r"((uint32_t)(nCols)))
#define TCGEN05_RELINQUISH() \
    asm volatile("tcgen05.relinquish_alloc_permit.cta_group::1.sync.aligned;")
#define TCGEN05_COMMIT(mbar) \
    asm volatile("tcgen05.commit.cta_group::1.mbarrier::arrive::one.shared::cluster.b64 [%0];" \
                 :: "r"((uint32_t)(mbar)) : "memory")
#define TCGEN05_WAIT_LD() \
    asm volatile("tcgen05.wait::ld.sync.aligned;" ::: "memory")
#define TCGEN05_FENCE_BEFORE() \
    asm volatile("tcgen05.fence::before_thread_sync;" ::: "memory")
#define TCGEN05_FENCE_AFTER() \
    asm volatile("tcgen05.fence::after_thread_sync;" ::: "memory")
#define FENCE_PROXY_ASYNC_SHARED_CTA() \
    asm volatile("fence.proxy.async.shared::cta;" ::: "memory")

#define TCGEN05_LD_32X32B_X32(r, tmem_addr) \
    asm volatile( \
        "tcgen05.ld.sync.aligned.32x32b.x32.b32 " \
        "{%0, %1, %2, %3, %4, %5, %6, %7, " \
        " %8, %9, %10, %11, %12, %13, %14, %15, " \
        " %16, %17, %18, %19, %20, %21, %22, %23, " \
        " %24, %25, %26, %27, %28, %29, %30, %31}, [%32];" \
        : "=r"((r)[0]),  "=r"((r)[1]),  "=r"((r)[2]),  "=r"((r)[3]), \
          "=r"((r)[4]),  "=r"((r)[5]),  "=r"((r)[6]),  "=r"((r)[7]), \
          "=r"((r)[8]),  "=r"((r)[9]),  "=r"((r)[10]), "=r"((r)[11]), \
          "=r"((r)[12]), "=r"((r)[13]), "=r"((r)[14]), "=r"((r)[15]), \
          "=r"((r)[16]), "=r"((r)[17]), "=r"((r)[18]), "=r"((r)[19]), \
          "=r"((r)[20]), "=r"((r)[21]), "=r"((r)[22]), "=r"((r)[23]), \
          "=r"((r)[24]), "=r"((r)[25]), "=r"((r)[26]), "=r"((r)[27]), \
          "=r"((r)[28]), "=r"((r)[29]), "=r"((r)[30]), "=r"((r)[31]) \
        : "r"(tmem_addr))

#if HAVE_TCGEN05
__device__ __forceinline__ void mma_f16_ss(uint32_t d, uint64_t da, uint64_t db,
                                           uint32_t idesc, uint32_t en) {
    asm volatile(
        "{\n\t.reg .pred p;\n\tsetp.ne.u32 p, %4, 0;\n\t"
        "tcgen05.mma.cta_group::1.kind::f16 [%0], %1, %2, %3, {%5, %5, %5, %5}, p;\n\t}"
        :: "r"(d), "l"(da), "l"(db), "r"(idesc), "r"(en), "r"(0u) : "memory");
}
#endif

// SW64 K-major smem descriptor: layout=4 (SW64), version=1, SBO=32, LBO=1
__device__ __forceinline__ uint64_t make_desc_sw64(uint32_t base) {
    const uint64_t BASE =
        (uint64_t(4) << 61) | (uint64_t(1) << 46) | (uint64_t(32) << 32) | (uint64_t(1) << 16);
    return BASE | ((uint64_t)(base >> 4) & 0x3FFF);
}

#define SW64S(o) ((o) ^ (((o) >> 3) & 0x30))

// cp.async helpers
#define CP_ASYNC16(dst, src) \
    asm volatile("cp.async.cg.shared.global [%0], [%1], 16;" :: "r"(dst), "l"(src) : "memory")
#define CP_COMMIT() asm volatile("cp.async.commit_group;" ::: "memory")
#define CP_WAIT1()  asm volatile("cp.async.wait_group 1;" ::: "memory")

// ---------------- mma.sync helper (baseline PTX) --------------------------
__device__ __forceinline__ void mma_bf16(float* c, const uint32_t* a, const uint32_t* b) {
    asm volatile(
        "mma.sync.aligned.m16n8k16.row.col.f32.bf16.bf16.f32 "
        "{%0,%1,%2,%3}, {%4,%5,%6,%7}, {%8,%9}, {%0,%1,%2,%3};"
        : "+f"(c[0]), "+f"(c[1]), "+f"(c[2]), "+f"(c[3])
        : "r"(a[0]), "r"(a[1]), "r"(a[2]), "r"(a[3]), "r"(b[0]), "r"(b[1]));
}

// ---------------- kernel 1: gate softmax ----------------------------------
__global__ void gate_kernel(const float* __restrict__ x,
                            const float* __restrict__ gw,
                            const float* __restrict__ gb) {
    int gwarp = (blockIdx.x * blockDim.x + threadIdx.x) >> 5;
    int lane = threadIdx.x & 31;
    if (gwarp >= T_TOKENS) return;
    const float* xr = x + (size_t)gwarp * DIN;
    float acc[N_EXP];
#pragma unroll
    for (int e = 0; e < N_EXP; e++) acc[e] = 0.f;
    for (int i = lane; i < DIN; i += 32) {
        float xv = xr[i];
        const float* gwr = gw + (size_t)i * N_EXP;
#pragma unroll
        for (int e = 0; e < N_EXP; e++) acc[e] += xv * gwr[e];
    }
#pragma unroll
    for (int off = 16; off; off >>= 1)
#pragma unroll
        for (int e = 0; e < N_EXP; e++)
            acc[e] += __shfl_xor_sync(0xffffffffu, acc[e], off);
    if (lane == 0) {
        float m = -1e30f;
#pragma unroll
        for (int e = 0; e < N_EXP; e++) { acc[e] += gb[e]; m = fmaxf(m, acc[e]); }
        float s = 0.f;
#pragma unroll
        for (int e = 0; e < N_EXP; e++) { acc[e] = __expf(acc[e] - m); s += acc[e]; }
        float inv = 1.0f / s;
#pragma unroll
        for (int e = 0; e < N_EXP; e++) g_gates[gwarp * N_EXP + e] = acc[e] * inv;
    }
}

// ---------------- kernel 2: gate-prescale + split x -----------------------
// A'_e[t,i] = g[t,e] * x[t,i], split into bf16 hi/lo. One block per token.
__global__ void prescale_x_kernel(const float* __restrict__ x) {
    int idx = blockIdx.x * blockDim.x + threadIdx.x;   // float4 index; t = idx/256
    int t = idx >> 8;                                  // DIN/4 = 256
    float4 v = ((const float4*)x)[idx];
    const float* gp = g_gates + (size_t)t * N_EXP;
#pragma unroll
    for (int e = 0; e < N_EXP; e++) {
        float g = gp[e];
        float a = g * v.x, b = g * v.y, c = g * v.z, d = g * v.w;
        __nv_bfloat16 h0 = __float2bfloat16(a), h1 = __float2bfloat16(b);
        __nv_bfloat16 h2 = __float2bfloat16(c), h3 = __float2bfloat16(d);
        __nv_bfloat16 l0 = __float2bfloat16(a - __bfloat162float(h0));
        __nv_bfloat16 l1 = __float2bfloat16(b - __bfloat162float(h1));
        __nv_bfloat16 l2 = __float2bfloat16(c - __bfloat162float(h2));
        __nv_bfloat16 l3 = __float2bfloat16(d - __bfloat162float(h3));
        __nv_bfloat162* ph = (__nv_bfloat162*)(g_axh + (size_t)e * T_TOKENS * DIN);
        __nv_bfloat162* pl = (__nv_bfloat162*)(g_axl + (size_t)e * T_TOKENS * DIN);
        ph[2 * idx]     = __nv_bfloat162(h0, h1);
        ph[2 * idx + 1] = __nv_bfloat162(h2, h3);
        pl[2 * idx]     = __nv_bfloat162(l0, l1);
        pl[2 * idx + 1] = __nv_bfloat162(l2, l3);
    }
}

// ---------------- kernel 3: transpose + split W ---------------------------
__global__ void wsplit_kernel(const float* __restrict__ w) {
    __shared__ float tile[32][33];
    int e = blockIdx.z;
    int i0 = blockIdx.y * 32;
    int o0 = blockIdx.x * 32;
    int tx = threadIdx.x, ty = threadIdx.y;   // (32, 8)
    const float* wb = w + ((size_t)e << 20);
#pragma unroll
    for (int k = 0; k < 4; k++)
        tile[ty + 8 * k][tx] = wb[(size_t)(i0 + ty + 8 * k) * DOUT + o0 + tx];
    __syncthreads();
#pragma unroll
    for (int k = 0; k < 4; k++) {
        float v = tile[tx][ty + 8 * k];
        __nv_bfloat16 h = __float2bfloat16(v);
        __nv_bfloat16 l = __float2bfloat16(v - __bfloat162float(h));
        size_t idx = ((size_t)e << 20) + (size_t)(o0 + ty + 8 * k) * DIN + i0 + tx;
        g_wh[idx] = h;
        g_wl[idx] = l;
    }
}

// ---------------- kernel 4: main GEMM (dual path) -------------------------
__global__ void __launch_bounds__(256, 1)
moe_gemm_kernel(float* __restrict__ out) {
    extern __shared__ char smem[];
    int tid = threadIdx.x;
    int wid = tid >> 5;
    int lid = tid & 31;
    int nt = blockIdx.x;           // 0..3
    int mt = blockIdx.y;           // 0..31
    int t0 = mt * BM;
    int o0 = nt * BN;

#if HAVE_TCGEN05
    // ================== tcgen05 TMEM path (sm_103a) ======================
    // Single accumulation over all 8 experts (A is gate-prescaled).
    // D regions: (mblk, nblk) -> TMEM cols mblk*256 + nblk*128 (512 total).
    uint32_t sb = smem_u32(smem);
    const uint32_t MB[NSTAGE] = {sb + 8, sb + 16, sb + 24};
    const uint32_t IDESC = (1u << 4) | (1u << 7) | (1u << 10) |
                           ((128 / 8) << 17) | ((128 / 16) << 24);

    if (wid == 0) TCGEN05_ALLOC(sb, 512);
    if (tid == 0) {
        MBARRIER_INIT(MB[0], 1); MBARRIER_INIT(MB[1], 1); MBARRIER_INIT(MB[2], 1);
    }
    __syncthreads();
    uint32_t tb;
    asm volatile("ld.shared.b32 %0, [%1];" : "=r"(tb) : "r"(sb));

    const int CHUNKS = N_EXP * (DIN / BK);     // 256

    // chunk loader: 16 cp.async of 16 B per thread into stage s
    auto load_chunk = [&](int s, int c) {
        int e = c >> 5, kc = c & 31;
        const char* ah = (const char*)(g_axh + ((size_t)e * T_TOKENS + t0) * DIN + kc * BK);
        const char* al = (const char*)(g_axl + ((size_t)e * T_TOKENS + t0) * DIN + kc * BK);
        const char* bh = (const char*)(g_wh + ((size_t)e << 20) + (size_t)o0 * DIN + kc * BK);
        const char* bl = (const char*)(g_wl + ((size_t)e << 20) + (size_t)o0 * DIN + kc * BK);
        uint32_t sbase = sb + 1024 + (uint32_t)s * STAGE_B;
        const size_t rs = (size_t)DIN * 2;     // row stride in bytes
#pragma unroll
        for (int j = 0; j < 8; j++) {          // A: tensors 0..3
            int a = j * 256 + tid;             // 0..2047
            int ta = a >> 9;                   // 0..3: A0h A0l A1h A1l
            int mb = ta >> 1, hl = ta & 1;
            int r = (a >> 2) & 127, cc = a & 3;
            const char* src = (hl ? al : ah) + (size_t)(mb * 128 + r) * rs + cc * 16;
            uint32_t dst = sbase + ta * TILE_B + SW64S((uint32_t)(r * 64 + cc * 16));
            CP_ASYNC16(dst, src);
        }
#pragma unroll
        for (int j = 0; j < 8; j++) {          // B: tensors 4..7
            int a = j * 256 + tid;             // 0..2047
            int tbs = a >> 9;                  // 0..3: B0h B0l B1h B1l
            int nb = tbs >> 1, hl = tbs & 1;
            int r = (a >> 2) & 127, cc = a & 3;
            const char* src = (hl ? bl : bh) + (size_t)(nb * 128 + r) * rs + cc * 16;
            uint32_t dst = sbase + (4 + tbs) * TILE_B + SW64S((uint32_t)(r * 64 + cc * 16));
            CP_ASYNC16(dst, src);
        }
        CP_COMMIT();
    };

    // prologue: chunks 0,1 into stages 0,1
    load_chunk(0, 0);
    load_chunk(1, 1);

    int ph[NSTAGE] = {0, 0, 0};

    for (int c = 0; c < CHUNKS; c++) {
        int s = c % NSTAGE;

        // wait chunk c data (<=1 newer group outstanding), make visible
        CP_WAIT1();
        FENCE_PROXY_ASYNC_SHARED_CTA();
        __syncthreads();

        // issue MMAs for chunk c (keeps tensor queue fed while others load)
        if (wid == 0) {
            TCGEN05_FENCE_AFTER();
            if (elect_one()) {
                uint32_t sbase = sb + 1024 + (uint32_t)s * STAGE_B;
                uint64_t dA[4], dB[4];
#pragma unroll
                for (int i = 0; i < 4; i++) {
                    dA[i] = make_desc_sw64(sbase + i * TILE_B);
                    dB[i] = make_desc_sw64(sbase + (4 + i) * TILE_B);
                }
#pragma unroll
                for (int ks = 0; ks < 2; ks++) {
                    uint64_t off = (uint64_t)(ks * 2);     // 16 bf16 = 32 B
                    uint32_t en0 = (c == 0 && ks == 0) ? 0u : 1u;
#pragma unroll
                    for (int mb = 0; mb < 2; mb++)
#pragma unroll
                        for (int nb = 0; nb < 2; nb++) {
                            uint32_t dreg = tb + mb * 256 + nb * 128;
                            uint64_t ah = dA[mb * 2] + off, alo = dA[mb * 2 + 1] + off;
                            uint64_t bh = dB[nb * 2] + off, blo = dB[nb * 2 + 1] + off;
                            mma_f16_ss(dreg, ah,  bh,  IDESC, en0);
                            mma_f16_ss(dreg, ah,  blo, IDESC, 1u);
                            mma_f16_ss(dreg, alo, bh,  IDESC, 1u);
                        }
                }
                TCGEN05_COMMIT(MB[s]);
            }
        }

        // prefetch chunk c+2 into stage (c+2)%3 (guard: MMA(c-1) complete)
        int ls = (c + 2) % NSTAGE;
        if (c + 2 < CHUNKS) {
            if (c >= 1) { MBARRIER_WAIT_PARITY(MB[ls], ph[ls]); ph[ls] ^= 1; }
            load_chunk(ls, c + 2);
        } else {
            CP_COMMIT();   // keep group accounting uniform
        }
    }

    // drain the last three MMAs (one outstanding commit per stage)
    MBARRIER_WAIT_PARITY(MB[0], ph[0]);
    MBARRIER_WAIT_PARITY(MB[1], ph[1]);
    MBARRIER_WAIT_PARITY(MB[2], ph[2]);
    TCGEN05_FENCE_AFTER();

    // epilogue: single TMEM read + store (D already fully gated sum)
    {
        int mblk = wid >> 2;
        int row = (wid & 3) * 32 + lid;
        int my_t = t0 + mblk * 128 + row;
        float* orow = out + (size_t)my_t * DOUT + o0;
#pragma unroll
        for (int q = 0; q < 8; q++) {
            uint32_t tmp[32];
            TCGEN05_LD_32X32B_X32(tmp, tb + mblk * 256 + q * 32);
            TCGEN05_WAIT_LD();
#pragma unroll
            for (int v = 0; v < 8; v++) {
                float4 f4 = make_float4(__uint_as_float(tmp[4 * v]),
                                        __uint_as_float(tmp[4 * v + 1]),
                                        __uint_as_float(tmp[4 * v + 2]),
                                        __uint_as_float(tmp[4 * v + 3]));
                ((float4*)(orow + q * 32))[v] = f4;
            }
        }
        TCGEN05_FENCE_BEFORE();
    }

    __syncthreads();
    if (tid == 0) { MBARRIER_INVAL(MB[0]); MBARRIER_INVAL(MB[1]); MBARRIER_INVAL(MB[2]); }
    __syncthreads();
    if (wid == 0) { TCGEN05_RELINQUISH(); TCGEN05_DEALLOC(tb, 512); }

#else
    // ================== mma.sync HMMA fallback (baseline pass) ===========
    // Correctness-only path: 4 sequential 128x128 sub-tiles, prescaled A,
    // single accumulation (no per-expert epilogue).
    const int wr = wid >> 1;             // 0..3
    const int wc = wid & 1;              // 0..1
    const int tg = lid >> 2;
    const int tig = lid & 3;

    for (int half = 0; half < 2; half++) {
        for (int nh = 0; nh < 2; nh++) {
            int t0h = t0 + half * 128;
            int o0h = o0 + nh * 128;

            float C[64];
#pragma unroll
            for (int i = 0; i < 64; i++) C[i] = 0.f;

            auto load_chunk = [&](int s, int c) {
                int e = c >> 5, kc = c & 31;
                const uint4* Ah4 = (const uint4*)(g_axh + ((size_t)e * T_TOKENS + t0h) * DIN);
                const uint4* Al4 = (const uint4*)(g_axl + ((size_t)e * T_TOKENS + t0h) * DIN);
                const uint4* Bh4 = (const uint4*)(g_wh + ((size_t)e << 20) + (size_t)o0h * DIN);
                const uint4* Bl4 = (const uint4*)(g_wl + ((size_t)e << 20) + (size_t)o0h * DIN);
                char* dst = smem + s * 40960;
#pragma unroll
                for (int j = 0; j < 2; j++) {
                    int idx = j * 256 + tid;
                    int r2 = idx >> 2;
                    int c16 = idx & 3;
                    size_t g = (size_t)r2 * 128 + kc * 4 + c16;
                    uint32_t so = (uint32_t)r2 * 80 + c16 * 16;
                    uint4 vah = Ah4[g];
                    uint4 val = Al4[g];
                    uint4 vbh = Bh4[g];
                    uint4 vbl = Bl4[g];
                    *(uint4*)(dst + so)         = vah;
                    *(uint4*)(dst + 10240 + so) = val;
                    *(uint4*)(dst + 20480 + so) = vbh;
                    *(uint4*)(dst + 30720 + so) = vbl;
                }
            };

            auto compute = [&](int s) {
                const char* base = smem + s * 40960;
#pragma unroll
                for (int ks = 0; ks < 2; ks++) {
                    int kb = ks * 16;
                    uint32_t ah[2][4], al[2][4];
#pragma unroll
                    for (int m2 = 0; m2 < 2; m2++) {
                        int r0 = wr * 32 + m2 * 16 + tg;
                        const char* A0 = base + (uint32_t)r0 * 80 + (kb + tig * 2) * 2;
                        ah[m2][0] = *(const uint32_t*)(A0);
                        ah[m2][1] = *(const uint32_t*)(A0 + 8 * 80);
                        ah[m2][2] = *(const uint32_t*)(A0 + 16);
                        ah[m2][3] = *(const uint32_t*)(A0 + 8 * 80 + 16);
                        const char* A1 = A0 + 10240;
                        al[m2][0] = *(const uint32_t*)(A1);
                        al[m2][1] = *(const uint32_t*)(A1 + 8 * 80);
                        al[m2][2] = *(const uint32_t*)(A1 + 16);
                        al[m2][3] = *(const uint32_t*)(A1 + 8 * 80 + 16);
                    }
                    uint32_t bh[8][2], bl[8][2];
#pragma unroll
                    for (int n2 = 0; n2 < 8; n2++) {
                        int nr = wc * 64 + n2 * 8 + tg;
                        const char* B0 = base + 20480 + (uint32_t)nr * 80 + (kb + tig * 2) * 2;
                        bh[n2][0] = *(const uint32_t*)(B0);
                        bh[n2][1] = *(const uint32_t*)(B0 + 16);
                        const char* B1 = B0 + 10240;
                        bl[n2][0] = *(const uint32_t*)(B1);
                        bl[n2][1] = *(const uint32_t*)(B1 + 16);
                    }
#pragma unroll
                    for (int m2 = 0; m2 < 2; m2++)
#pragma unroll
                        for (int n2 = 0; n2 < 8; n2++) {
                            float* c = &C[(m2 * 8 + n2) * 4];
                            mma_bf16(c, ah[m2], bh[n2]);
                            mma_bf16(c, ah[m2], bl[n2]);
                            mma_bf16(c, al[m2], bh[n2]);
                        }
                }
            };

            load_chunk(0, 0);
            __syncthreads();
            for (int c = 0; c < 256; c++) {
                if (c < 255) load_chunk((c + 1) & 1, c + 1);
                compute(c & 1);
                __syncthreads();
            }

#pragma unroll
            for (int m2 = 0; m2 < 2; m2++)
#pragma unroll
                for (int n2 = 0; n2 < 8; n2++) {
                    int i = (m2 * 8 + n2) * 4;
                    size_t r = (size_t)(t0h + wr * 32 + m2 * 16 + tg);
                    size_t col = (size_t)(o0h + wc * 64 + n2 * 8 + tig * 2);
                    float2 v0 = make_float2(C[i + 0], C[i + 1]);
                    float2 v1 = make_float2(C[i + 2], C[i + 3]);
                    *(float2*)&out[r * DOUT + col]       = v0;
                    *(float2*)&out[(r + 8) * DOUT + col] = v1;
                }
            __syncthreads();
        }
    }
#endif
}

// ---------------- launch --------------------------------------------------
extern "C" void kernel_launch(void* const* d_in, const int* in_sizes, int n_in,
                              void* d_out, int out_size) {
    const float* x  = (const float*)d_in[0];
    const float* gw = (const float*)d_in[1];
    const float* gb = (const float*)d_in[2];
    const float* w  = (const float*)d_in[3];
    float* out = (float*)d_out;

    gate_kernel<<<T_TOKENS / 8, 256>>>(x, gw, gb);
    prescale_x_kernel<<<(T_TOKENS * DIN / 4) / 256, 256>>>(x);
    wsplit_kernel<<<dim3(DOUT / 32, DIN / 32, N_EXP), dim3(32, 8)>>>(w);

    cudaFuncSetAttribute(moe_gemm_kernel,
                         cudaFuncAttributeMaxDynamicSharedMemorySize, GEMM_SMEM);
    moe_gemm_kernel<<<dim3(DOUT / BN, T_TOKENS / BM), 256, GEMM_SMEM>>>(out);
}

// round 8
// speedup vs baseline: 2.3890x; 1.0772x over previous
#include <cuda_runtime.h>
#include <cuda.h>
#include <cuda_bf16.h>
#include <cstdint>

// ============================================================
// MoELayer: out[t,o] = sum_e softmax(x@gw+gb)[t,e] * (x[t,:] @ W[e,:,o])
// T=8192, D_IN=D_OUT=1024, E=8.
// R7: TMA-fed warp-specialized producer/consumer tcgen05 pipeline
//     (no per-chunk CTA barrier), fused gate+prescale prep.
// ============================================================

#define T_TOKENS 8192
#define DIN      1024
#define DOUT     1024
#define N_EXP    8

#define BM 256              // tokens per CTA (2 x 128 M-blocks)
#define BN 256              // out cols per CTA (2 x 128 N-blocks)
#define BK 32               // K chunk (64 B rows, SW64)

#define TILE_B   8192                     // 128 rows * 64 B
#define STAGE_B  (8 * TILE_B)             // A0h A0l A1h A1l B0h B0l B1h B1l = 64 KB
#define NSTAGE   3
#define GEMM_SMEM (1024 + NSTAGE * STAGE_B)   // 197632

// ---------------- device scratch ----------------------------------------
// per-expert gate-prescaled activations, bf16 hi/lo split: [e][t][i]
__device__ __nv_bfloat16  g_axh[(size_t)N_EXP * T_TOKENS * DIN];
__device__ __nv_bfloat16  g_axl[(size_t)N_EXP * T_TOKENS * DIN];
__device__ __nv_bfloat16  g_wh[N_EXP * DOUT * DIN];   // [e][o][i]  K-major
__device__ __nv_bfloat16  g_wl[N_EXP * DOUT * DIN];

// ---------------- arch-specific feature detection ------------------------
#if defined(__CUDA_ARCH_FEAT_SM103_ALL) || defined(__CUDA_ARCH_FEAT_SM100_ALL) || defined(__CUDA_ARCH_FEAT_SM101_ALL)
#define HAVE_TCGEN05 1
#else
#define HAVE_TCGEN05 0
#endif

// ---------------- common helpers -----------------------------------------
__device__ __forceinline__ uint32_t smem_u32(const void* p) {
    uint32_t a;
    asm("{ .reg .u64 t; cvta.to.shared.u64 t, %1; cvt.u32.u64 %0, t; }"
        : "=r"(a) : "l"(p));
    return a;
}

__device__ __forceinline__ uint32_t elect_one() {
    uint32_t p;
    asm volatile("{\n\t.reg .pred P;\n\telect.sync _|P, 0xFFFFFFFF;\n\t"
                 "selp.b32 %0, 1, 0, P;\n\t}" : "=r"(p));
    return p;
}

#define MBARRIER_INIT(addr, cnt) \
    asm volatile("mbarrier.init.shared.b64 [%0], %1;" :: "r"((uint32_t)(addr)), "r"((uint32_t)(cnt)) : "memory")
#define MBARRIER_INVAL(addr) \
    asm volatile("mbarrier.inval.shared.b64 [%0];" :: "r"((uint32_t)(addr)) : "memory")
#define MBARRIER_EXPECT_TX(addr, bytes) \
    asm volatile("mbarrier.arrive.expect_tx.shared.b64 _, [%0], %1;" \
                 :: "r"((uint32_t)(addr)), "r"((uint32_t)(bytes)) : "memory")

#define MBARRIER_WAIT_PARITY(mbar_smem_addr, phase_parity) do { \
    uint32_t _mbar = (uint32_t)(mbar_smem_addr); \
    uint32_t _parity = (uint32_t)(phase_parity); \
    uint32_t _done; \
    asm volatile( \
        "{\n\t.reg .pred p;\n\t" \
        "mbarrier.try_wait.parity.acquire.cta.shared::cta.b64 p, [%1], %2;\n\t" \
        "selp.b32 %0, 1, 0, p;\n\t}" \
        : "=r"(_done) : "r"(_mbar), "r"(_parity) : "memory"); \
    if (!_done) { \
        asm volatile( \
            "{\n\t.reg .pred P1;\n\t" \
            "WAIT_LOOP_%=:\n\t" \
            "mbarrier.try_wait.parity.acquire.cta.shared::cta.b64 P1, [%0], %1, 0x989680;\n\t" \
            "@P1 bra.uni WAIT_DONE_%=;\n\t" \
            "bra.uni WAIT_LOOP_%=;\n\t" \
            "WAIT_DONE_%=:\n\t}" \
            :: "r"(_mbar), "r"(_parity) : "memory"); \
    } \
} while (0)

#define TCGEN05_ALLOC(smem_addr, nCols) \
    asm volatile("tcgen05.alloc.cta_group::1.sync.aligned.shared::cta.b32 [%0], %1;" \
                 :: "r"((uint32_t)(smem_addr)), "r"((uint32_t)(nCols)) : "memory")
#define TCGEN05_DEALLOC(tmem_addr, nCols) \
    asm volatile("tcgen05.dealloc.cta_group::1.sync.aligned.b32 %0, %1;" \
                 :: "r"(tmem_addr), "r"((uint32_t)(nCols)))
#define TCGEN05_RELINQUISH() \
    asm volatile("tcgen05.relinquish_alloc_permit.cta_group::1.sync.aligned;")
#define TCGEN05_COMMIT(mbar) \
    asm volatile("tcgen05.commit.cta_group::1.mbarrier::arrive::one.shared::cluster.b64 [%0];" \
                 :: "r"((uint32_t)(mbar)) : "memory")
#define TCGEN05_WAIT_LD() \
    asm volatile("tcgen05.wait::ld.sync.aligned;" ::: "memory")
#define TCGEN05_FENCE_BEFORE() \
    asm volatile("tcgen05.fence::before_thread_sync;" ::: "memory")
#define TCGEN05_FENCE_AFTER() \
    asm volatile("tcgen05.fence::after_thread_sync;" ::: "memory")

#define TCGEN05_LD_32X32B_X32(r, tmem_addr) \
    asm volatile( \
        "tcgen05.ld.sync.aligned.32x32b.x32.b32 " \
        "{%0, %1, %2, %3, %4, %5, %6, %7, " \
        " %8, %9, %10, %11, %12, %13, %14, %15, " \
        " %16, %17, %18, %19, %20, %21, %22, %23, " \
        " %24, %25, %26, %27, %28, %29, %30, %31}, [%32];" \
        : "=r"((r)[0]),  "=r"((r)[1]),  "=r"((r)[2]),  "=r"((r)[3]), \
          "=r"((r)[4]),  "=r"((r)[5]),  "=r"((r)[6]),  "=r"((r)[7]), \
          "=r"((r)[8]),  "=r"((r)[9]),  "=r"((r)[10]), "=r"((r)[11]), \
          "=r"((r)[12]), "=r"((r)[13]), "=r"((r)[14]), "=r"((r)[15]), \
          "=r"((r)[16]), "=r"((r)[17]), "=r"((r)[18]), "=r"((r)[19]), \
          "=r"((r)[20]), "=r"((r)[21]), "=r"((r)[22]), "=r"((r)[23]), \
          "=r"((r)[24]), "=r"((r)[25]), "=r"((r)[26]), "=r"((r)[27]), \
          "=r"((r)[28]), "=r"((r)[29]), "=r"((r)[30]), "=r"((r)[31]) \
        : "r"(tmem_addr))

#if HAVE_TCGEN05
__device__ __forceinline__ void mma_f16_ss(uint32_t d, uint64_t da, uint64_t db,
                                           uint32_t idesc, uint32_t en) {
    asm volatile(
        "{\n\t.reg .pred p;\n\tsetp.ne.u32 p, %4, 0;\n\t"
        "tcgen05.mma.cta_group::1.kind::f16 [%0], %1, %2, %3, {%5, %5, %5, %5}, p;\n\t}"
        :: "r"(d), "l"(da), "l"(db), "r"(idesc), "r"(en), "r"(0u) : "memory");
}
#endif

// SW64 K-major smem descriptor: layout=4 (SW64), version=1, SBO=32, LBO=1
__device__ __forceinline__ uint64_t make_desc_sw64(uint32_t base) {
    const uint64_t BASE =
        (uint64_t(4) << 61) | (uint64_t(1) << 46) | (uint64_t(32) << 32) | (uint64_t(1) << 16);
    return BASE | ((uint64_t)(base >> 4) & 0x3FFF);
}

// 2D TMA load into SMEM (mbarrier complete_tx)
#define TMA2D(dst, mapptr, cx, cy, bar) \
    asm volatile("cp.async.bulk.tensor.2d.shared::cta.global.tile.mbarrier::complete_tx::bytes " \
                 "[%0], [%1, {%2, %3}], [%4];" \
                 :: "r"((uint32_t)(dst)), "l"(mapptr), "r"((int)(cx)), "r"((int)(cy)), \
                    "r"((uint32_t)(bar)) : "memory")

// ---------------- mma.sync helper (baseline PTX) --------------------------
__device__ __forceinline__ void mma_bf16(float* c, const uint32_t* a, const uint32_t* b) {
    asm volatile(
        "mma.sync.aligned.m16n8k16.row.col.f32.bf16.bf16.f32 "
        "{%0,%1,%2,%3}, {%4,%5,%6,%7}, {%8,%9}, {%0,%1,%2,%3};"
        : "+f"(c[0]), "+f"(c[1]), "+f"(c[2]), "+f"(c[3])
        : "r"(a[0]), "r"(a[1]), "r"(a[2]), "r"(a[3]), "r"(b[0]), "r"(b[1]));
}

// ---------------- kernel 1: fused gate softmax + prescale + split ---------
// One warp per token: gate logits (shfl-reduced -> all lanes), softmax,
// then write A'_e = g_e * x as bf16 hi/lo splits.
__global__ void gate_prescale_kernel(const float* __restrict__ x,
                                     const float* __restrict__ gw,
                                     const float* __restrict__ gb) {
    int t = (blockIdx.x * blockDim.x + threadIdx.x) >> 5;
    int lane = threadIdx.x & 31;
    const float2* x2 = (const float2*)x + (size_t)t * (DIN / 2);

    float2 xs[16];
    float acc[N_EXP];
#pragma unroll
    for (int e = 0; e < N_EXP; e++) acc[e] = 0.f;
#pragma unroll
    for (int k = 0; k < 16; k++) {
        float2 v = x2[lane + 32 * k];
        xs[k] = v;
        const float* g0 = gw + (size_t)(2 * (lane + 32 * k)) * N_EXP;
#pragma unroll
        for (int e = 0; e < N_EXP; e++)
            acc[e] += v.x * g0[e] + v.y * g0[N_EXP + e];
    }
#pragma unroll
    for (int off = 16; off; off >>= 1)
#pragma unroll
        for (int e = 0; e < N_EXP; e++)
            acc[e] += __shfl_xor_sync(0xffffffffu, acc[e], off);

    // softmax (replicated across lanes)
    float m = -1e30f;
#pragma unroll
    for (int e = 0; e < N_EXP; e++) { acc[e] += gb[e]; m = fmaxf(m, acc[e]); }
    float s = 0.f;
#pragma unroll
    for (int e = 0; e < N_EXP; e++) { acc[e] = __expf(acc[e] - m); s += acc[e]; }
    float inv = 1.0f / s;

#pragma unroll
    for (int e = 0; e < N_EXP; e++) {
        float g = acc[e] * inv;
        __nv_bfloat162* ph = (__nv_bfloat162*)(g_axh + ((size_t)e * T_TOKENS + t) * DIN);
        __nv_bfloat162* pl = (__nv_bfloat162*)(g_axl + ((size_t)e * T_TOKENS + t) * DIN);
#pragma unroll
        for (int k = 0; k < 16; k++) {
            float a = g * xs[k].x;
            float b = g * xs[k].y;
            __nv_bfloat16 h0 = __float2bfloat16(a);
            __nv_bfloat16 h1 = __float2bfloat16(b);
            __nv_bfloat16 l0 = __float2bfloat16(a - __bfloat162float(h0));
            __nv_bfloat16 l1 = __float2bfloat16(b - __bfloat162float(h1));
            ph[lane + 32 * k] = __nv_bfloat162(h0, h1);
            pl[lane + 32 * k] = __nv_bfloat162(l0, l1);
        }
    }
}

// ---------------- kernel 2: transpose + split W ---------------------------
__global__ void wsplit_kernel(const float* __restrict__ w) {
    __shared__ float tile[32][33];
    int e = blockIdx.z;
    int i0 = blockIdx.y * 32;
    int o0 = blockIdx.x * 32;
    int tx = threadIdx.x, ty = threadIdx.y;   // (32, 8)
    const float* wb = w + ((size_t)e << 20);
#pragma unroll
    for (int k = 0; k < 4; k++)
        tile[ty + 8 * k][tx] = wb[(size_t)(i0 + ty + 8 * k) * DOUT + o0 + tx];
    __syncthreads();
#pragma unroll
    for (int k = 0; k < 4; k++) {
        float v = tile[tx][ty + 8 * k];
        __nv_bfloat16 h = __float2bfloat16(v);
        __nv_bfloat16 l = __float2bfloat16(v - __bfloat162float(h));
        size_t idx = ((size_t)e << 20) + (size_t)(o0 + ty + 8 * k) * DIN + i0 + tx;
        g_wh[idx] = h;
        g_wl[idx] = l;
    }
}

// ---------------- kernel 3: main GEMM (dual path) -------------------------
__global__ void __launch_bounds__(256, 1)
moe_gemm_kernel(float* __restrict__ out,
                const __grid_constant__ CUtensorMap tm_ah,
                const __grid_constant__ CUtensorMap tm_al,
                const __grid_constant__ CUtensorMap tm_wh,
                const __grid_constant__ CUtensorMap tm_wl) {
    extern __shared__ char smem[];
    int tid = threadIdx.x;
    int wid = tid >> 5;
    int lid = tid & 31;
    int nt = blockIdx.x;           // 0..3
    int mt = blockIdx.y;           // 0..31
    int t0 = mt * BM;
    int o0 = nt * BN;

#if HAVE_TCGEN05
    // ================== tcgen05 TMA producer/consumer ====================
    uint32_t sb = smem_u32(smem);
    const uint32_t FULL0  = sb + 8;    // full[s]  = FULL0  + 8*s
    const uint32_t EMPTY0 = sb + 32;   // empty[s] = EMPTY0 + 8*s
    const uint32_t DONE   = sb + 56;
    const uint32_t IDESC = (1u << 4) | (1u << 7) | (1u << 10) |
                           ((128 / 8) << 17) | ((128 / 16) << 24);
    const int CHUNKS = N_EXP * (DIN / BK);     // 256

    if (wid == 0) TCGEN05_ALLOC(sb, 512);
    if (tid == 0) {
#pragma unroll
        for (int s = 0; s < NSTAGE; s++) {
            MBARRIER_INIT(FULL0 + 8 * s, 1);
            MBARRIER_INIT(EMPTY0 + 8 * s, 1);
        }
        MBARRIER_INIT(DONE, 1);
    }
    __syncthreads();
    uint32_t tb;
    asm volatile("ld.shared.b32 %0, [%1];" : "=r"(tb) : "r"(sb));

    if (wid == 0) {
        // ---------------- producer: TMA loads ----------------
        int pe[NSTAGE] = {0, 0, 0};
        for (int c = 0; c < CHUNKS; c++) {
            int s = c % NSTAGE;
            int e = c >> 5, kc = c & 31;
            if (c >= NSTAGE) { MBARRIER_WAIT_PARITY(EMPTY0 + 8 * s, pe[s]); pe[s] ^= 1; }
            if (elect_one()) {
                uint32_t sbase = sb + 1024 + (uint32_t)s * STAGE_B;
                uint32_t fb = FULL0 + 8 * s;
                int cx = kc * BK;
                int ya = e * T_TOKENS + t0;
                int yb = e * DOUT + o0;
                MBARRIER_EXPECT_TX(fb, STAGE_B);
                TMA2D(sbase,              &tm_ah, cx, ya,       fb);
                TMA2D(sbase + 1 * TILE_B, &tm_al, cx, ya,       fb);
                TMA2D(sbase + 2 * TILE_B, &tm_ah, cx, ya + 128, fb);
                TMA2D(sbase + 3 * TILE_B, &tm_al, cx, ya + 128, fb);
                TMA2D(sbase + 4 * TILE_B, &tm_wh, cx, yb,       fb);
                TMA2D(sbase + 5 * TILE_B, &tm_wl, cx, yb,       fb);
                TMA2D(sbase + 6 * TILE_B, &tm_wh, cx, yb + 128, fb);
                TMA2D(sbase + 7 * TILE_B, &tm_wl, cx, yb + 128, fb);
            }
        }
    } else if (wid == 1) {
        // ---------------- consumer: MMA issue ----------------
        int pf[NSTAGE] = {0, 0, 0};
        for (int c = 0; c < CHUNKS; c++) {
            int s = c % NSTAGE;
            MBARRIER_WAIT_PARITY(FULL0 + 8 * s, pf[s]); pf[s] ^= 1;
            if (elect_one()) {
                uint32_t sbase = sb + 1024 + (uint32_t)s * STAGE_B;
                uint64_t dA[4], dB[4];
#pragma unroll
                for (int i = 0; i < 4; i++) {
                    dA[i] = make_desc_sw64(sbase + i * TILE_B);
                    dB[i] = make_desc_sw64(sbase + (4 + i) * TILE_B);
                }
#pragma unroll
                for (int ks = 0; ks < 2; ks++) {
                    uint64_t off = (uint64_t)(ks * 2);     // 16 bf16 = 32 B
                    uint32_t en0 = (c == 0 && ks == 0) ? 0u : 1u;
#pragma unroll
                    for (int mb = 0; mb < 2; mb++)
#pragma unroll
                        for (int nb = 0; nb < 2; nb++) {
                            uint32_t dreg = tb + mb * 256 + nb * 128;
                            uint64_t ah = dA[mb * 2] + off, alo = dA[mb * 2 + 1] + off;
                            uint64_t bh = dB[nb * 2] + off, blo = dB[nb * 2 + 1] + off;
                            mma_f16_ss(dreg, ah,  bh,  IDESC, en0);
                            mma_f16_ss(dreg, ah,  blo, IDESC, 1u);
                            mma_f16_ss(dreg, alo, bh,  IDESC, 1u);
                        }
                }
                TCGEN05_COMMIT(EMPTY0 + 8 * s);
            }
        }
        // final commit: DONE arrives when ALL prior MMAs complete
        if (elect_one()) TCGEN05_COMMIT(DONE);
    }
    // warps 2..7 fall through

    __syncthreads();                 // ensures DONE commit was issued
    MBARRIER_WAIT_PARITY(DONE, 0);
    TCGEN05_FENCE_AFTER();

    // epilogue: single TMEM read + store
    {
        int mblk = wid >> 2;
        int row = (wid & 3) * 32 + lid;
        int my_t = t0 + mblk * 128 + row;
        float* orow = out + (size_t)my_t * DOUT + o0;
#pragma unroll
        for (int q = 0; q < 8; q++) {
            uint32_t tmp[32];
            TCGEN05_LD_32X32B_X32(tmp, tb + mblk * 256 + q * 32);
            TCGEN05_WAIT_LD();
#pragma unroll
            for (int v = 0; v < 8; v++) {
                float4 f4 = make_float4(__uint_as_float(tmp[4 * v]),
                                        __uint_as_float(tmp[4 * v + 1]),
                                        __uint_as_float(tmp[4 * v + 2]),
                                        __uint_as_float(tmp[4 * v + 3]));
                ((float4*)(orow + q * 32))[v] = f4;
            }
        }
        TCGEN05_FENCE_BEFORE();
    }

    __syncthreads();
    if (tid == 0) {
#pragma unroll
        for (int s = 0; s < NSTAGE; s++) {
            MBARRIER_INVAL(FULL0 + 8 * s);
            MBARRIER_INVAL(EMPTY0 + 8 * s);
        }
        MBARRIER_INVAL(DONE);
    }
    __syncthreads();
    if (wid == 0) { TCGEN05_RELINQUISH(); TCGEN05_DEALLOC(tb, 512); }

#else
    // ================== mma.sync HMMA fallback (baseline pass) ===========
    const int wr = wid >> 1;
    const int wc = wid & 1;
    const int tg = lid >> 2;
    const int tig = lid & 3;

    for (int half = 0; half < 2; half++) {
        for (int nh = 0; nh < 2; nh++) {
            int t0h = t0 + half * 128;
            int o0h = o0 + nh * 128;

            float C[64];
#pragma unroll
            for (int i = 0; i < 64; i++) C[i] = 0.f;

            auto load_chunk = [&](int s, int c) {
                int e = c >> 5, kc = c & 31;
                const uint4* Ah4 = (const uint4*)(g_axh + ((size_t)e * T_TOKENS + t0h) * DIN);
                const uint4* Al4 = (const uint4*)(g_axl + ((size_t)e * T_TOKENS + t0h) * DIN);
                const uint4* Bh4 = (const uint4*)(g_wh + ((size_t)e << 20) + (size_t)o0h * DIN);
                const uint4* Bl4 = (const uint4*)(g_wl + ((size_t)e << 20) + (size_t)o0h * DIN);
                char* dst = smem + s * 40960;
#pragma unroll
                for (int j = 0; j < 2; j++) {
                    int idx = j * 256 + tid;
                    int r2 = idx >> 2;
                    int c16 = idx & 3;
                    size_t g = (size_t)r2 * 128 + kc * 4 + c16;
                    uint32_t so = (uint32_t)r2 * 80 + c16 * 16;
                    uint4 vah = Ah4[g];
                    uint4 val = Al4[g];
                    uint4 vbh = Bh4[g];
                    uint4 vbl = Bl4[g];
                    *(uint4*)(dst + so)         = vah;
                    *(uint4*)(dst + 10240 + so) = val;
                    *(uint4*)(dst + 20480 + so) = vbh;
                    *(uint4*)(dst + 30720 + so) = vbl;
                }
            };

            auto compute = [&](int s) {
                const char* base = smem + s * 40960;
#pragma unroll
                for (int ks = 0; ks < 2; ks++) {
                    int kb = ks * 16;
                    uint32_t ah[2][4], al[2][4];
#pragma unroll
                    for (int m2 = 0; m2 < 2; m2++) {
                        int r0 = wr * 32 + m2 * 16 + tg;
                        const char* A0 = base + (uint32_t)r0 * 80 + (kb + tig * 2) * 2;
                        ah[m2][0] = *(const uint32_t*)(A0);
                        ah[m2][1] = *(const uint32_t*)(A0 + 8 * 80);
                        ah[m2][2] = *(const uint32_t*)(A0 + 16);
                        ah[m2][3] = *(const uint32_t*)(A0 + 8 * 80 + 16);
                        const char* A1 = A0 + 10240;
                        al[m2][0] = *(const uint32_t*)(A1);
                        al[m2][1] = *(const uint32_t*)(A1 + 8 * 80);
                        al[m2][2] = *(const uint32_t*)(A1 + 16);
                        al[m2][3] = *(const uint32_t*)(A1 + 8 * 80 + 16);
                    }
                    uint32_t bh[8][2], bl[8][2];
#pragma unroll
                    for (int n2 = 0; n2 < 8; n2++) {
                        int nr = wc * 64 + n2 * 8 + tg;
                        const char* B0 = base + 20480 + (uint32_t)nr * 80 + (kb + tig * 2) * 2;
                        bh[n2][0] = *(const uint32_t*)(B0);
                        bh[n2][1] = *(const uint32_t*)(B0 + 16);
                        const char* B1 = B0 + 10240;
                        bl[n2][0] = *(const uint32_t*)(B1);
                        bl[n2][1] = *(const uint32_t*)(B1 + 16);
                    }
#pragma unroll
                    for (int m2 = 0; m2 < 2; m2++)
#pragma unroll
                        for (int n2 = 0; n2 < 8; n2++) {
                            float* c = &C[(m2 * 8 + n2) * 4];
                            mma_bf16(c, ah[m2], bh[n2]);
                            mma_bf16(c, ah[m2], bl[n2]);
                            mma_bf16(c, al[m2], bh[n2]);
                        }
                }
            };

            load_chunk(0, 0);
            __syncthreads();
            for (int c = 0; c < 256; c++) {
                if (c < 255) load_chunk((c + 1) & 1, c + 1);
                compute(c & 1);
                __syncthreads();
            }

#pragma unroll
            for (int m2 = 0; m2 < 2; m2++)
#pragma unroll
                for (int n2 = 0; n2 < 8; n2++) {
                    int i = (m2 * 8 + n2) * 4;
                    size_t r = (size_t)(t0h + wr * 32 + m2 * 16 + tg);
                    size_t col = (size_t)(o0h + wc * 64 + n2 * 8 + tig * 2);
                    float2 v0 = make_float2(C[i + 0], C[i + 1]);
                    float2 v1 = make_float2(C[i + 2], C[i + 3]);
                    *(float2*)&out[r * DOUT + col]       = v0;
                    *(float2*)&out[(r + 8) * DOUT + col] = v1;
                }
            __syncthreads();
        }
    }
#endif
}

// ---------------- host: tensor-map setup + launch -------------------------
typedef CUresult (*EncodeTiledFn)(
    CUtensorMap*, CUtensorMapDataType, cuuint32_t, void*,
    const cuuint64_t*, const cuuint64_t*, const cuuint32_t*, const cuuint32_t*,
    CUtensorMapInterleave, CUtensorMapSwizzle, CUtensorMapL2promotion,
    CUtensorMapFloatOOBfill);

static void make_map_2d(EncodeTiledFn enc, CUtensorMap* m, void* ptr, uint64_t rows) {
    cuuint64_t dims[2]    = {(cuuint64_t)DIN, (cuuint64_t)rows};
    cuuint64_t strides[1] = {(cuuint64_t)DIN * 2};
    cuuint32_t box[2]     = {(cuuint32_t)BK, 128};
    cuuint32_t es[2]      = {1, 1};
    enc(m, CU_TENSOR_MAP_DATA_TYPE_BFLOAT16, 2, ptr, dims, strides, box, es,
        CU_TENSOR_MAP_INTERLEAVE_NONE, CU_TENSOR_MAP_SWIZZLE_64B,
        CU_TENSOR_MAP_L2_PROMOTION_L2_128B, CU_TENSOR_MAP_FLOAT_OOB_FILL_NONE);
}

extern "C" void kernel_launch(void* const* d_in, const int* in_sizes, int n_in,
                              void* d_out, int out_size) {
    const float* x  = (const float*)d_in[0];
    const float* gw = (const float*)d_in[1];
    const float* gb = (const float*)d_in[2];
    const float* w  = (const float*)d_in[3];
    float* out = (float*)d_out;

    static CUtensorMap s_maps[4];
    static bool s_init = false;
    if (!s_init) {
        void* fn = nullptr;
        cudaDriverEntryPointQueryResult qr;
        cudaGetDriverEntryPoint("cuTensorMapEncodeTiled", &fn, cudaEnableDefault, &qr);
        EncodeTiledFn enc = (EncodeTiledFn)fn;
        void *pah, *pal, *pwh, *pwl;
        cudaGetSymbolAddress(&pah, g_axh);
        cudaGetSymbolAddress(&pal, g_axl);
        cudaGetSymbolAddress(&pwh, g_wh);
        cudaGetSymbolAddress(&pwl, g_wl);
        make_map_2d(enc, &s_maps[0], pah, (uint64_t)N_EXP * T_TOKENS);
        make_map_2d(enc, &s_maps[1], pal, (uint64_t)N_EXP * T_TOKENS);
        make_map_2d(enc, &s_maps[2], pwh, (uint64_t)N_EXP * DOUT);
        make_map_2d(enc, &s_maps[3], pwl, (uint64_t)N_EXP * DOUT);
        s_init = true;
    }

    gate_prescale_kernel<<<T_TOKENS / 8, 256>>>(x, gw, gb);
    wsplit_kernel<<<dim3(DOUT / 32, DIN / 32, N_EXP), dim3(32, 8)>>>(w);

    cudaFuncSetAttribute(moe_gemm_kernel,
                         cudaFuncAttributeMaxDynamicSharedMemorySize, GEMM_SMEM);
    moe_gemm_kernel<<<dim3(DOUT / BN, T_TOKENS / BM), 256, GEMM_SMEM>>>(
        out, s_maps[0], s_maps[1], s_maps[2], s_maps[3]);
}

// round 9
// speedup vs baseline: 4.7589x; 1.9920x over previous
#include <cuda_runtime.h>
#include <cuda.h>
#include <cuda_bf16.h>
#include <cuda_fp16.h>
#include <cstdint>

// ============================================================
// MoELayer: out[t,o] = sum_e softmax(x@gw+gb)[t,e] * (x[t,:] @ W[e,:,o])
// T=8192, D_IN=D_OUT=1024, E=8.
// R9: single-product fp16 tcgen05 GEMM (fp32 TMEM accum).
//     A' = fp16(g_e * x) per expert (128 MB, coalesced), W = fp16.
//     TMA producer/consumer pipeline (R7 structure), BK=64 SW128.
// ============================================================

#define T_TOKENS 8192
#define DIN      1024
#define DOUT     1024
#define N_EXP    8

#define BM 256              // tokens per CTA (2 x 128 M-blocks)
#define BN 256              // out cols per CTA (2 x 128 N-blocks)
#define BK 64               // K chunk (128 B fp16 rows, SW128)

#define TILE_B   16384                    // 128 rows * 128 B
#define STAGE_B  (4 * TILE_B)             // A0 A1 B0 B1 = 64 KB
#define NSTAGE   3
#define GEMM_SMEM (1024 + NSTAGE * STAGE_B)   // 197632

// ---------------- device scratch ----------------------------------------
__device__ float   g_gates[T_TOKENS * N_EXP];
__device__ __half  g_ah[(size_t)N_EXP * T_TOKENS * DIN];   // fp16(g_e * x)  [e][t][i]
__device__ __half  g_wh16[(size_t)N_EXP * DOUT * DIN];     // fp16(W^T)      [e][o][i]

// ---------------- arch-specific feature detection ------------------------
#if defined(__CUDA_ARCH_FEAT_SM103_ALL) || defined(__CUDA_ARCH_FEAT_SM100_ALL) || defined(__CUDA_ARCH_FEAT_SM101_ALL)
#define HAVE_TCGEN05 1
#else
#define HAVE_TCGEN05 0
#endif

// ---------------- common helpers -----------------------------------------
__device__ __forceinline__ uint32_t smem_u32(const void* p) {
    uint32_t a;
    asm("{ .reg .u64 t; cvta.to.shared.u64 t, %1; cvt.u32.u64 %0, t; }"
        : "=r"(a) : "l"(p));
    return a;
}

__device__ __forceinline__ uint32_t elect_one() {
    uint32_t p;
    asm volatile("{\n\t.reg .pred P;\n\telect.sync _|P, 0xFFFFFFFF;\n\t"
                 "selp.b32 %0, 1, 0, P;\n\t}" : "=r"(p));
    return p;
}

#define MBARRIER_INIT(addr, cnt) \
    asm volatile("mbarrier.init.shared.b64 [%0], %1;" :: "r"((uint32_t)(addr)), "r"((uint32_t)(cnt)) : "memory")
#define MBARRIER_INVAL(addr) \
    asm volatile("mbarrier.inval.shared.b64 [%0];" :: "r"((uint32_t)(addr)) : "memory")
#define MBARRIER_EXPECT_TX(addr, bytes) \
    asm volatile("mbarrier.arrive.expect_tx.shared.b64 _, [%0], %1;" \
                 :: "r"((uint32_t)(addr)), "r"((uint32_t)(bytes)) : "memory")

#define MBARRIER_WAIT_PARITY(mbar_smem_addr, phase_parity) do { \
    uint32_t _mbar = (uint32_t)(mbar_smem_addr); \
    uint32_t _parity = (uint32_t)(phase_parity); \
    uint32_t _done; \
    asm volatile( \
        "{\n\t.reg .pred p;\n\t" \
        "mbarrier.try_wait.parity.acquire.cta.shared::cta.b64 p, [%1], %2;\n\t" \
        "selp.b32 %0, 1, 0, p;\n\t}" \
        : "=r"(_done) : "r"(_mbar), "r"(_parity) : "memory"); \
    if (!_done) { \
        asm volatile( \
            "{\n\t.reg .pred P1;\n\t" \
            "WAIT_LOOP_%=:\n\t" \
            "mbarrier.try_wait.parity.acquire.cta.shared::cta.b64 P1, [%0], %1, 0x989680;\n\t" \
            "@P1 bra.uni WAIT_DONE_%=;\n\t" \
            "bra.uni WAIT_LOOP_%=;\n\t" \
            "WAIT_DONE_%=:\n\t}" \
            :: "r"(_mbar), "r"(_parity) : "memory"); \
    } \
} while (0)

#define TCGEN05_ALLOC(smem_addr, nCols) \
    asm volatile("tcgen05.alloc.cta_group::1.sync.aligned.shared::cta.b32 [%0], %1;" \
                 :: "r"((uint32_t)(smem_addr)), "r"((uint32_t)(nCols)) : "memory")
#define TCGEN05_DEALLOC(tmem_addr, nCols) \
    asm volatile("tcgen05.dealloc.cta_group::1.sync.aligned.b32 %0, %1;" \
                 :: "r"(tmem_addr), "r"((uint32_t)(nCols)))
#define TCGEN05_RELINQUISH() \
    asm volatile("tcgen05.relinquish_alloc_permit.cta_group::1.sync.aligned;")
#define TCGEN05_COMMIT(mbar) \
    asm volatile("tcgen05.commit.cta_group::1.mbarrier::arrive::one.shared::cluster.b64 [%0];" \
                 :: "r"((uint32_t)(mbar)) : "memory")
#define TCGEN05_WAIT_LD() \
    asm volatile("tcgen05.wait::ld.sync.aligned;" ::: "memory")
#define TCGEN05_FENCE_BEFORE() \
    asm volatile("tcgen05.fence::before_thread_sync;" ::: "memory")
#define TCGEN05_FENCE_AFTER() \
    asm volatile("tcgen05.fence::after_thread_sync;" ::: "memory")

#define TCGEN05_LD_32X32B_X32(r, tmem_addr) \
    asm volatile( \
        "tcgen05.ld.sync.aligned.32x32b.x32.b32 " \
        "{%0, %1, %2, %3, %4, %5, %6, %7, " \
        " %8, %9, %10, %11, %12, %13, %14, %15, " \
        " %16, %17, %18, %19, %20, %21, %22, %23, " \
        " %24, %25, %26, %27, %28, %29, %30, %31}, [%32];" \
        : "=r"((r)[0]),  "=r"((r)[1]),  "=r"((r)[2]),  "=r"((r)[3]), \
          "=r"((r)[4]),  "=r"((r)[5]),  "=r"((r)[6]),  "=r"((r)[7]), \
          "=r"((r)[8]),  "=r"((r)[9]),  "=r"((r)[10]), "=r"((r)[11]), \
          "=r"((r)[12]), "=r"((r)[13]), "=r"((r)[14]), "=r"((r)[15]), \
          "=r"((r)[16]), "=r"((r)[17]), "=r"((r)[18]), "=r"((r)[19]), \
          "=r"((r)[20]), "=r"((r)[21]), "=r"((r)[22]), "=r"((r)[23]), \
          "=r"((r)[24]), "=r"((r)[25]), "=r"((r)[26]), "=r"((r)[27]), \
          "=r"((r)[28]), "=r"((r)[29]), "=r"((r)[30]), "=r"((r)[31]) \
        : "r"(tmem_addr))

#if HAVE_TCGEN05
__device__ __forceinline__ void mma_f16_ss(uint32_t d, uint64_t da, uint64_t db,
                                           uint32_t idesc, uint32_t en) {
    asm volatile(
        "{\n\t.reg .pred p;\n\tsetp.ne.u32 p, %4, 0;\n\t"
        "tcgen05.mma.cta_group::1.kind::f16 [%0], %1, %2, %3, {%5, %5, %5, %5}, p;\n\t}"
        :: "r"(d), "l"(da), "l"(db), "r"(idesc), "r"(en), "r"(0u) : "memory");
}
#endif

// SW128 K-major smem descriptor (layout=SW128, version=1, SBO=64, LBO=1)
__device__ __forceinline__ uint64_t make_desc_sw128(uint32_t base) {
    const uint64_t BASE =
        (uint64_t(2) << 61) | (uint64_t(1) << 46) | (uint64_t(64) << 32) | (uint64_t(1) << 16);
    return BASE | ((uint64_t)(base >> 4) & 0x3FFF);
}

// 2D TMA load into SMEM (mbarrier complete_tx)
#define TMA2D(dst, mapptr, cx, cy, bar) \
    asm volatile("cp.async.bulk.tensor.2d.shared::cta.global.tile.mbarrier::complete_tx::bytes " \
                 "[%0], [%1, {%2, %3}], [%4];" \
                 :: "r"((uint32_t)(dst)), "l"(mapptr), "r"((int)(cx)), "r"((int)(cy)), \
                    "r"((uint32_t)(bar)) : "memory")

// ---------------- mma.sync helper (baseline PTX, fp16) --------------------
__device__ __forceinline__ void mma_fp16(float* c, const uint32_t* a, const uint32_t* b) {
    asm volatile(
        "mma.sync.aligned.m16n8k16.row.col.f32.f16.f16.f32 "
        "{%0,%1,%2,%3}, {%4,%5,%6,%7}, {%8,%9}, {%0,%1,%2,%3};"
        : "+f"(c[0]), "+f"(c[1]), "+f"(c[2]), "+f"(c[3])
        : "r"(a[0]), "r"(a[1]), "r"(a[2]), "r"(a[3]), "r"(b[0]), "r"(b[1]));
}

// ---------------- kernel 1: gate softmax ----------------------------------
__global__ void gate_kernel(const float* __restrict__ x,
                            const float* __restrict__ gw,
                            const float* __restrict__ gb) {
    int t = (blockIdx.x * blockDim.x + threadIdx.x) >> 5;
    int lane = threadIdx.x & 31;
    if (t >= T_TOKENS) return;
    const float* xr = x + (size_t)t * DIN;
    float acc[N_EXP];
#pragma unroll
    for (int e = 0; e < N_EXP; e++) acc[e] = 0.f;
    for (int i = lane; i < DIN; i += 32) {
        float xv = xr[i];
        const float* gwr = gw + (size_t)i * N_EXP;
#pragma unroll
        for (int e = 0; e < N_EXP; e++) acc[e] += xv * gwr[e];
    }
#pragma unroll
    for (int off = 16; off; off >>= 1)
#pragma unroll
        for (int e = 0; e < N_EXP; e++)
            acc[e] += __shfl_xor_sync(0xffffffffu, acc[e], off);
    if (lane == 0) {
        float m = -1e30f;
#pragma unroll
        for (int e = 0; e < N_EXP; e++) { acc[e] += gb[e]; m = fmaxf(m, acc[e]); }
        float s = 0.f;
#pragma unroll
        for (int e = 0; e < N_EXP; e++) { acc[e] = __expf(acc[e] - m); s += acc[e]; }
        float inv = 1.0f / s;
#pragma unroll
        for (int e = 0; e < N_EXP; e++) g_gates[t * N_EXP + e] = acc[e] * inv;
    }
}

// ---------------- kernel 2: prescale to fp16 (coalesced 16B stores) -------
// thread = 8 consecutive elements of one token; per expert one 16B store.
__global__ void prescale_fp16_kernel(const float* __restrict__ x) {
    int idx = blockIdx.x * blockDim.x + threadIdx.x;   // 8-elem group id
    int t  = idx >> 7;                                 // DIN/8 = 128 groups/token
    int gi = idx & 127;
    const float4* xp = (const float4*)x + (size_t)idx * 2;
    float4 v0 = xp[0], v1 = xp[1];
    const float* gp = g_gates + (size_t)t * N_EXP;
#pragma unroll
    for (int e = 0; e < N_EXP; e++) {
        float g = gp[e];
        __half2 h0 = __floats2half2_rn(g * v0.x, g * v0.y);
        __half2 h1 = __floats2half2_rn(g * v0.z, g * v0.w);
        __half2 h2 = __floats2half2_rn(g * v1.x, g * v1.y);
        __half2 h3 = __floats2half2_rn(g * v1.z, g * v1.w);
        uint4 pk;
        pk.x = *reinterpret_cast<uint32_t*>(&h0);
        pk.y = *reinterpret_cast<uint32_t*>(&h1);
        pk.z = *reinterpret_cast<uint32_t*>(&h2);
        pk.w = *reinterpret_cast<uint32_t*>(&h3);
        uint4* dst = (uint4*)(g_ah + ((size_t)e * T_TOKENS + t) * DIN);
        dst[gi] = pk;
    }
}

// ---------------- kernel 3: transpose + convert W to fp16 -----------------
// W[e][i][o] -> g_wh16[e][o][i], 64x64 tiles, half2 vectorized stores.
__global__ void wsplit_fp16_kernel(const float* __restrict__ w) {
    __shared__ float tile[64][65];
    int e = blockIdx.z;
    int i0 = blockIdx.y * 64;
    int o0 = blockIdx.x * 64;
    int tid = threadIdx.x;     // 256
    const float* wb = w + ((size_t)e << 20);
#pragma unroll
    for (int j = 0; j < 16; j++) {
        int idx = j * 256 + tid;            // 0..4095
        int il = idx >> 6, ol = idx & 63;
        tile[il][ol] = wb[(size_t)(i0 + il) * DOUT + o0 + ol];
    }
    __syncthreads();
    __half* dst = g_wh16 + ((size_t)e << 20);
#pragma unroll
    for (int j = 0; j < 8; j++) {
        int idx = j * 256 + tid;            // 0..2047 half2 units
        int ol = idx >> 5, i2 = idx & 31;
        __half2 h = __floats2half2_rn(tile[2 * i2][ol], tile[2 * i2 + 1][ol]);
        *(__half2*)(dst + (size_t)(o0 + ol) * DIN + i0 + 2 * i2) = h;
    }
}

// ---------------- kernel 4: main GEMM (dual path) -------------------------
__global__ void __launch_bounds__(256, 1)
moe_gemm_kernel(float* __restrict__ out,
                const __grid_constant__ CUtensorMap tm_a,
                const __grid_constant__ CUtensorMap tm_w) {
    extern __shared__ char smem[];
    int tid = threadIdx.x;
    int wid = tid >> 5;
    int lid = tid & 31;
    int nt = blockIdx.x;           // 0..3
    int mt = blockIdx.y;           // 0..31
    int t0 = mt * BM;
    int o0 = nt * BN;

#if HAVE_TCGEN05
    // ================== tcgen05 TMA producer/consumer ====================
    uint32_t sb = smem_u32(smem);
    const uint32_t FULL0  = sb + 8;    // full[s]  = FULL0  + 8*s
    const uint32_t EMPTY0 = sb + 32;   // empty[s] = EMPTY0 + 8*s
    const uint32_t DONE   = sb + 56;
    // fp16: dtype F32, atype/btype FP16(=0), N=128, M=128
    const uint32_t IDESC = (1u << 4) | ((128 / 8) << 17) | ((128 / 16) << 24);
    const int CHUNKS = N_EXP * (DIN / BK);     // 128

    if (wid == 0) TCGEN05_ALLOC(sb, 512);
    if (tid == 0) {
#pragma unroll
        for (int s = 0; s < NSTAGE; s++) {
            MBARRIER_INIT(FULL0 + 8 * s, 1);
            MBARRIER_INIT(EMPTY0 + 8 * s, 1);
        }
        MBARRIER_INIT(DONE, 1);
    }
    __syncthreads();
    uint32_t tb;
    asm volatile("ld.shared.b32 %0, [%1];" : "=r"(tb) : "r"(sb));

    if (wid == 0) {
        // ---------------- producer: TMA loads ----------------
        int pe[NSTAGE] = {0, 0, 0};
        for (int c = 0; c < CHUNKS; c++) {
            int s = c % NSTAGE;
            int e = c >> 4, kc = c & 15;
            if (c >= NSTAGE) { MBARRIER_WAIT_PARITY(EMPTY0 + 8 * s, pe[s]); pe[s] ^= 1; }
            if (elect_one()) {
                uint32_t sbase = sb + 1024 + (uint32_t)s * STAGE_B;
                uint32_t fb = FULL0 + 8 * s;
                int cx = kc * BK;
                int ya = e * T_TOKENS + t0;
                int yb = e * DOUT + o0;
                MBARRIER_EXPECT_TX(fb, STAGE_B);
                TMA2D(sbase,              &tm_a, cx, ya,       fb);
                TMA2D(sbase + 1 * TILE_B, &tm_a, cx, ya + 128, fb);
                TMA2D(sbase + 2 * TILE_B, &tm_w, cx, yb,       fb);
                TMA2D(sbase + 3 * TILE_B, &tm_w, cx, yb + 128, fb);
            }
        }
    } else if (wid == 1) {
        // ---------------- consumer: MMA issue ----------------
        int pf[NSTAGE] = {0, 0, 0};
        for (int c = 0; c < CHUNKS; c++) {
            int s = c % NSTAGE;
            MBARRIER_WAIT_PARITY(FULL0 + 8 * s, pf[s]); pf[s] ^= 1;
            if (elect_one()) {
                uint32_t sbase = sb + 1024 + (uint32_t)s * STAGE_B;
                uint64_t dA0 = make_desc_sw128(sbase);
                uint64_t dA1 = make_desc_sw128(sbase + 1 * TILE_B);
                uint64_t dB0 = make_desc_sw128(sbase + 2 * TILE_B);
                uint64_t dB1 = make_desc_sw128(sbase + 3 * TILE_B);
#pragma unroll
                for (int ks = 0; ks < 4; ks++) {
                    uint64_t off = (uint64_t)(ks * 2);     // 16 fp16 = 32 B
                    uint32_t en0 = (c == 0 && ks == 0) ? 0u : 1u;
                    mma_f16_ss(tb,             dA0 + off, dB0 + off, IDESC, en0);
                    mma_f16_ss(tb + 128,       dA0 + off, dB1 + off, IDESC, en0);
                    mma_f16_ss(tb + 256,       dA1 + off, dB0 + off, IDESC, en0);
                    mma_f16_ss(tb + 256 + 128, dA1 + off, dB1 + off, IDESC, en0);
                }
                TCGEN05_COMMIT(EMPTY0 + 8 * s);
            }
        }
        if (elect_one()) TCGEN05_COMMIT(DONE);
    }
    // warps 2..7 fall through

    __syncthreads();                 // ensures DONE commit was issued
    MBARRIER_WAIT_PARITY(DONE, 0);
    TCGEN05_FENCE_AFTER();

    // epilogue: single TMEM read + store
    {
        int mblk = wid >> 2;
        int row = (wid & 3) * 32 + lid;
        int my_t = t0 + mblk * 128 + row;
        float* orow = out + (size_t)my_t * DOUT + o0;
#pragma unroll
        for (int q = 0; q < 8; q++) {
            uint32_t tmp[32];
            TCGEN05_LD_32X32B_X32(tmp, tb + mblk * 256 + q * 32);
            TCGEN05_WAIT_LD();
#pragma unroll
            for (int v = 0; v < 8; v++) {
                float4 f4 = make_float4(__uint_as_float(tmp[4 * v]),
                                        __uint_as_float(tmp[4 * v + 1]),
                                        __uint_as_float(tmp[4 * v + 2]),
                                        __uint_as_float(tmp[4 * v + 3]));
                ((float4*)(orow + q * 32))[v] = f4;
            }
        }
        TCGEN05_FENCE_BEFORE();
    }

    __syncthreads();
    if (tid == 0) {
#pragma unroll
        for (int s = 0; s < NSTAGE; s++) {
            MBARRIER_INVAL(FULL0 + 8 * s);
            MBARRIER_INVAL(EMPTY0 + 8 * s);
        }
        MBARRIER_INVAL(DONE);
    }
    __syncthreads();
    if (wid == 0) { TCGEN05_RELINQUISH(); TCGEN05_DEALLOC(tb, 512); }

#else
    // ================== mma.sync HMMA fallback (baseline pass) ===========
    // Compile-only fallback (measurements prove the tcgen05 pass is live).
    const int wr = wid >> 1;
    const int wc = wid & 1;
    const int tg = lid >> 2;
    const int tig = lid & 3;

    for (int half = 0; half < 2; half++) {
        for (int nh = 0; nh < 2; nh++) {
            int t0h = t0 + half * 128;
            int o0h = o0 + nh * 128;

            float C[64];
#pragma unroll
            for (int i = 0; i < 64; i++) C[i] = 0.f;

            // stage: A @0 (128 rows x 80B pitch, 32 fp16/row), B @10240
            auto load_chunk = [&](int s, int c) {
                int e = c >> 5, kc = c & 31;
                const uint4* A4 = (const uint4*)(g_ah + ((size_t)e * T_TOKENS + t0h) * DIN);
                const uint4* B4 = (const uint4*)(g_wh16 + ((size_t)e << 20) + (size_t)o0h * DIN);
                char* dst = smem + s * 20480;
#pragma unroll
                for (int j = 0; j < 2; j++) {
                    int idx = j * 256 + tid;          // 0..511
                    int r2 = idx >> 2;
                    int c16 = idx & 3;
                    size_t g = (size_t)r2 * 128 + kc * 4 + c16;
                    uint32_t so = (uint32_t)r2 * 80 + c16 * 16;
                    uint4 va = A4[g];
                    uint4 vb = B4[g];
                    *(uint4*)(dst + so)         = va;
                    *(uint4*)(dst + 10240 + so) = vb;
                }
            };

            auto compute = [&](int s) {
                const char* base = smem + s * 20480;
#pragma unroll
                for (int ks = 0; ks < 2; ks++) {
                    int kb = ks * 16;
                    uint32_t a[2][4];
#pragma unroll
                    for (int m2 = 0; m2 < 2; m2++) {
                        int r0 = wr * 32 + m2 * 16 + tg;
                        const char* A0 = base + (uint32_t)r0 * 80 + (kb + tig * 2) * 2;
                        a[m2][0] = *(const uint32_t*)(A0);
                        a[m2][1] = *(const uint32_t*)(A0 + 8 * 80);
                        a[m2][2] = *(const uint32_t*)(A0 + 16);
                        a[m2][3] = *(const uint32_t*)(A0 + 8 * 80 + 16);
                    }
                    uint32_t b[8][2];
#pragma unroll
                    for (int n2 = 0; n2 < 8; n2++) {
                        int nr = wc * 64 + n2 * 8 + tg;
                        const char* B0 = base + 10240 + (uint32_t)nr * 80 + (kb + tig * 2) * 2;
                        b[n2][0] = *(const uint32_t*)(B0);
                        b[n2][1] = *(const uint32_t*)(B0 + 16);
                    }
#pragma unroll
                    for (int m2 = 0; m2 < 2; m2++)
#pragma unroll
                        for (int n2 = 0; n2 < 8; n2++)
                            mma_fp16(&C[(m2 * 8 + n2) * 4], a[m2], b[n2]);
                }
            };

            load_chunk(0, 0);
            __syncthreads();
            for (int c = 0; c < 256; c++) {
                if (c < 255) load_chunk((c + 1) & 1, c + 1);
                compute(c & 1);
                __syncthreads();
            }

#pragma unroll
            for (int m2 = 0; m2 < 2; m2++)
#pragma unroll
                for (int n2 = 0; n2 < 8; n2++) {
                    int i = (m2 * 8 + n2) * 4;
                    size_t r = (size_t)(t0h + wr * 32 + m2 * 16 + tg);
                    size_t col = (size_t)(o0h + wc * 64 + n2 * 8 + tig * 2);
                    float2 v0 = make_float2(C[i + 0], C[i + 1]);
                    float2 v1 = make_float2(C[i + 2], C[i + 3]);
                    *(float2*)&out[r * DOUT + col]       = v0;
                    *(float2*)&out[(r + 8) * DOUT + col] = v1;
                }
            __syncthreads();
        }
    }
#endif
}

// ---------------- host: tensor-map setup + launch -------------------------
typedef CUresult (*EncodeTiledFn)(
    CUtensorMap*, CUtensorMapDataType, cuuint32_t, void*,
    const cuuint64_t*, const cuuint64_t*, const cuuint32_t*, const cuuint32_t*,
    CUtensorMapInterleave, CUtensorMapSwizzle, CUtensorMapL2promotion,
    CUtensorMapFloatOOBfill);

static void make_map_2d(EncodeTiledFn enc, CUtensorMap* m, void* ptr, uint64_t rows) {
    cuuint64_t dims[2]    = {(cuuint64_t)DIN, (cuuint64_t)rows};
    cuuint64_t strides[1] = {(cuuint64_t)DIN * 2};
    cuuint32_t box[2]     = {(cuuint32_t)BK, 128};   // 64 fp16 = 128 B = SW128 span
    cuuint32_t es[2]      = {1, 1};
    enc(m, CU_TENSOR_MAP_DATA_TYPE_FLOAT16, 2, ptr, dims, strides, box, es,
        CU_TENSOR_MAP_INTERLEAVE_NONE, CU_TENSOR_MAP_SWIZZLE_128B,
        CU_TENSOR_MAP_L2_PROMOTION_L2_128B, CU_TENSOR_MAP_FLOAT_OOB_FILL_NONE);
}

extern "C" void kernel_launch(void* const* d_in, const int* in_sizes, int n_in,
                              void* d_out, int out_size) {
    const float* x  = (const float*)d_in[0];
    const float* gw = (const float*)d_in[1];
    const float* gb = (const float*)d_in[2];
    const float* w  = (const float*)d_in[3];
    float* out = (float*)d_out;

    static CUtensorMap s_maps[2];
    static bool s_init = false;
    if (!s_init) {
        void* fn = nullptr;
        cudaDriverEntryPointQueryResult qr;
        cudaGetDriverEntryPoint("cuTensorMapEncodeTiled", &fn, cudaEnableDefault, &qr);
        EncodeTiledFn enc = (EncodeTiledFn)fn;
        void *pa, *pw;
        cudaGetSymbolAddress(&pa, g_ah);
        cudaGetSymbolAddress(&pw, g_wh16);
        make_map_2d(enc, &s_maps[0], pa, (uint64_t)N_EXP * T_TOKENS);
        make_map_2d(enc, &s_maps[1], pw, (uint64_t)N_EXP * DOUT);
        s_init = true;
    }

    gate_kernel<<<T_TOKENS / 8, 256>>>(x, gw, gb);
    prescale_fp16_kernel<<<(T_TOKENS * DIN / 8) / 256, 256>>>(x);
    wsplit_fp16_kernel<<<dim3(DOUT / 64, DIN / 64, N_EXP), 256>>>(w);

    cudaFuncSetAttribute(moe_gemm_kernel,
                         cudaFuncAttributeMaxDynamicSharedMemorySize, GEMM_SMEM);
    moe_gemm_kernel<<<dim3(DOUT / BN, T_TOKENS / BM), 256, GEMM_SMEM>>>(
        out, s_maps[0], s_maps[1]);
}